// round 12
// baseline (speedup 1.0000x reference)
#include <cuda_runtime.h>
#include <cuda_bf16.h>
#include <math.h>
#include <stdint.h>

// Problem constants
#define BB   4
#define W_   2000
#define I_   64
#define S_   64
#define T_   24
#define U_   32
#define US_  2
#define PER_ 2161
#define NND  8644
#define EMAX 147456

// weight regions in g_Bh/g_Bl (bf16 element offsets)
#define OFF_G0   0            // G0^T [1024,1024]
#define OFF_G1   1048576      // G1^T [1024,1024]
#define OFF_G2   2097152      // G2^T [512,1024]
#define OFF_TXTP 2621440      // W_txt plain [384(pad300),1024]
#define OFF_IMGT 3014656      // W_img^T [1024,2048]
#define OFF_TXTF 5111808      // fused (W_txt@G0)^T [1024,384]
#define BTOT     5505024

// ---------------- scratch (device globals; no allocation) ----------------
__device__ float g_F[(size_t)NND * 1024];
__device__ __nv_bfloat16 g_Aah[(size_t)NND * 1024];  // APa hi
__device__ __nv_bfloat16 g_Aal[(size_t)NND * 1024];  // APa lo
__device__ __nv_bfloat16 g_Abh[(size_t)NND * 1024];  // APb hi
__device__ __nv_bfloat16 g_Abl[(size_t)NND * 1024];  // APb lo
__device__ __nv_bfloat16 g_Imh[256 * 2048];
__device__ __nv_bfloat16 g_Iml[256 * 2048];
__device__ __nv_bfloat16 g_Bh[BTOT];
__device__ __nv_bfloat16 g_Bl[BTOT];
__device__ float g_bT[1024];            // b_txt @ G0
__device__ float g_SF[BB * S_ * 300];
__device__ float g_EL[NND * 4];
__device__ float g_ER[NND * 4];
__device__ int   g_deg[NND + 1];
__device__ int   g_off[NND + 1];
__device__ int   g_cur[NND];
__device__ int   g_esrc[EMAX];
__device__ unsigned char g_A1f[NND], g_R1f[NND];
__device__ int   g_list1[NND], g_listR[NND];
__device__ int   g_cnt1, g_cntR;

__device__ __forceinline__ uint32_t smem_u32(const void* p) {
    uint32_t a;
    asm("{ .reg .u64 t; cvta.to.shared.u64 t, %1; cvt.u32.u64 %0, t; }" : "=r"(a) : "l"(p));
    return a;
}

// ---------------- mma.sync / cp.async helpers ----------------
__device__ __forceinline__ void ldsm_x4(uint32_t* r, uint32_t addr) {
    asm volatile("ldmatrix.sync.aligned.m8n8.x4.shared.b16 {%0,%1,%2,%3}, [%4];"
                 : "=r"(r[0]), "=r"(r[1]), "=r"(r[2]), "=r"(r[3]) : "r"(addr));
}
__device__ __forceinline__ void ldsm_x2(uint32_t* r, uint32_t addr) {
    asm volatile("ldmatrix.sync.aligned.m8n8.x2.shared.b16 {%0,%1}, [%2];"
                 : "=r"(r[0]), "=r"(r[1]) : "r"(addr));
}
__device__ __forceinline__ void mma16816(float* c, const uint32_t* a, const uint32_t* b) {
    asm volatile(
        "mma.sync.aligned.m16n8k16.row.col.f32.bf16.bf16.f32 "
        "{%0,%1,%2,%3},{%4,%5,%6,%7},{%8,%9},{%0,%1,%2,%3};"
        : "+f"(c[0]), "+f"(c[1]), "+f"(c[2]), "+f"(c[3])
        : "r"(a[0]), "r"(a[1]), "r"(a[2]), "r"(a[3]), "r"(b[0]), "r"(b[1]));
}
__device__ __forceinline__ void cpa16(uint32_t dst, const void* src, int sz) {
    asm volatile("cp.async.cg.shared.global [%0], [%1], 16, %2;"
                 :: "r"(dst), "l"(src), "r"(sz));
}
__device__ __forceinline__ void cpa_commit() {
    asm volatile("cp.async.commit_group;");
}
template <int N>
__device__ __forceinline__ void cpa_wait() {
    asm volatile("cp.async.wait_group %0;" :: "n"(N));
}

// ---------------- selectors ----------------
__device__ __forceinline__ const __nv_bfloat16* sel_Ah(int s) {
    if (s == 1) return g_Aah;
    if (s == 2) return g_Abh;
    if (s == 3) return g_Imh;
    return g_Bh + OFF_G0;                 // 4: G0^T as A operand
}
__device__ __forceinline__ const __nv_bfloat16* sel_Al(int s) {
    if (s == 1) return g_Aal;
    if (s == 2) return g_Abl;
    if (s == 3) return g_Iml;
    return g_Bl + OFF_G0;
}
__device__ __forceinline__ const int* sel_list(int s, const int* ext) {
    if (s == 1) return g_list1;
    if (s == 2) return g_listR;
    if (s == 3) return ext;
    return nullptr;
}
__device__ __forceinline__ const int* sel_cnt(int s) {
    if (s == 1) return &g_cnt1;
    if (s == 2) return &g_cntR;
    return nullptr;
}
__device__ __forceinline__ int img_row(int r) {
    return (r / I_) * PER_ + W_ + (r % I_);
}

__device__ __forceinline__ void split_store(__nv_bfloat16* ph, __nv_bfloat16* pl, float v) {
    __nv_bfloat16 h = __float2bfloat16(v);
    __nv_bfloat16 l = __float2bfloat16(v - __bfloat162float(h));
    *ph = h; *pl = l;
}

// write a 300-dim feature into APa split (ld=384, zero-padded)
__device__ __forceinline__ void feat_out(int node, int tid, float v0, float v1, float v2) {
    size_t base = (size_t)node * 384;
    split_store(g_Aah + base + tid, g_Aal + base + tid, v0);
    split_store(g_Aah + base + tid + 128, g_Aal + base + tid + 128, v1);
    int d2 = tid + 256;
    if (d2 < 300) {
        split_store(g_Aah + base + d2, g_Aal + base + d2, v2);
    } else {
        g_Aah[base + d2] = __float2bfloat16(0.f);
        g_Aal[base + d2] = __float2bfloat16(0.f);
    }
}

// ---------------- staged feature kernels ----------------
__global__ void k_feat1(const int* __restrict__ aw,
                        const int* __restrict__ sent, const float* __restrict__ smask,
                        const float* __restrict__ we) {
    int node = blockIdx.x;
    int b = node / PER_, p = node - b * PER_;
    int tid = threadIdx.x;
    float v0 = 0.f, v1 = 0.f, v2 = 0.f;

    if (p < W_) {
        const float* row = we + (size_t)aw[(size_t)b * W_ + p] * 300;
        v0 = row[tid]; v1 = row[tid + 128];
        if (tid < 44) v2 = row[tid + 256];
    } else if (p >= W_ + I_ && p < W_ + I_ + S_) {
        int s = p - (W_ + I_);
        const int*   sw = sent + ((size_t)b * S_ + s) * T_;
        const float* mk = smask + ((size_t)b * S_ + s) * T_;
        float c = 0.f, a0 = 0.f, a1 = 0.f, a2 = 0.f;
#pragma unroll 4
        for (int t = 0; t < T_; t++) {
            float m = mk[t]; c += m;
            const float* row = we + (size_t)sw[t] * 300;
            a0 += m * row[tid];
            a1 += m * row[tid + 128];
            if (tid < 44) a2 += m * row[tid + 256];
        }
        float inv = 1.f / (c == 0.f ? 1.f : c);
        v0 = a0 * inv; v1 = a1 * inv; v2 = a2 * inv;
        float* sf = g_SF + ((size_t)b * S_ + s) * 300;
        sf[tid] = v0; sf[tid + 128] = v1;
        if (tid < 44) sf[tid + 256] = v2;
    } else if (p >= W_ + I_ + S_) {
        return;
    }
    feat_out(node, tid, v0, v1, v2);
}

__device__ __forceinline__ void utt_from_cache(const int* __restrict__ utts,
                                               const float* __restrict__ umask,
                                               int b, int u, int tid,
                                               float& o0, float& o1, float& o2) {
    float c = 0.f, a0 = 0.f, a1 = 0.f, a2 = 0.f;
#pragma unroll
    for (int t = 0; t < US_; t++) {
        size_t e = ((size_t)b * U_ + u) * US_ + t;
        float m = umask[e]; c += m;
        const float* sf = g_SF + ((size_t)b * S_ + utts[e]) * 300;
        a0 += m * sf[tid];
        a1 += m * sf[tid + 128];
        if (tid < 44) a2 += m * sf[tid + 256];
    }
    float inv = 1.f / (c == 0.f ? 1.f : c);
    o0 = a0 * inv; o1 = a1 * inv; o2 = a2 * inv;
}

__global__ void k_feat23(const int* __restrict__ utts, const float* __restrict__ umask) {
    int i = blockIdx.x;
    int b = i / (U_ + 1), q = i - b * (U_ + 1);
    int tid = threadIdx.x;
    if (q < U_) {
        float v0, v1, v2;
        utt_from_cache(utts, umask, b, q, tid, v0, v1, v2);
        feat_out(b * PER_ + W_ + I_ + S_ + q, tid, v0, v1, v2);
    } else {
        float a0 = 0.f, a1 = 0.f, a2 = 0.f;
        for (int u = 0; u < U_; u++) {
            float t0, t1, t2;
            utt_from_cache(utts, umask, b, u, tid, t0, t1, t2);
            a0 += t0; a1 += t1; a2 += t2;
        }
        const float inv = 1.f / (float)U_;
        feat_out(b * PER_ + W_ + I_ + S_ + U_, tid, a0 * inv, a1 * inv, a2 * inv);
    }
}

// ---------------- image feats split ----------------
__global__ void k_splitImg(const float* __restrict__ A) {
    long total = 256L * 2048 / 4;
    long stride = (long)gridDim.x * blockDim.x;
    for (long i = (long)blockIdx.x * blockDim.x + threadIdx.x; i < total; i += stride) {
        long e = i * 4;
        float4 v = *(const float4*)(A + e);
        __nv_bfloat16 h0 = __float2bfloat16(v.x), h1 = __float2bfloat16(v.y);
        __nv_bfloat16 h2 = __float2bfloat16(v.z), h3 = __float2bfloat16(v.w);
        g_Imh[e] = h0; g_Imh[e+1] = h1; g_Imh[e+2] = h2; g_Imh[e+3] = h3;
        g_Iml[e]   = __float2bfloat16(v.x - __bfloat162float(h0));
        g_Iml[e+1] = __float2bfloat16(v.y - __bfloat162float(h1));
        g_Iml[e+2] = __float2bfloat16(v.z - __bfloat162float(h2));
        g_Iml[e+3] = __float2bfloat16(v.w - __bfloat162float(h3));
    }
}

// ---------------- weight splits: 4 transposed + 1 plain ----------------
__global__ void k_splitWall(const float* __restrict__ g0, const float* __restrict__ g1,
                            const float* __restrict__ g2, const float* __restrict__ wt,
                            const float* __restrict__ wi) {
    int z = blockIdx.z;
    int tx = threadIdx.x, ty = threadIdx.y;
    if (z != 3) {
        // transposed: output [N, K] from input [K, N]
        const float* W; int N, K; size_t off;
        if (z == 0)      { W = g0; N = 1024; K = 1024; off = OFF_G0; }
        else if (z == 1) { W = g1; N = 1024; K = 1024; off = OFF_G1; }
        else if (z == 2) { W = g2; N = 512;  K = 1024; off = OFF_G2; }
        else             { W = wi; N = 1024; K = 2048; off = OFF_IMGT; }
        int KP = K;
        int nt = blockIdx.x * 32, kt = blockIdx.y * 32;
        if (nt >= N || kt >= KP) return;
        __shared__ float tile[32][33];
#pragma unroll
        for (int i = 0; i < 4; i++) {
            int k = kt + ty + i * 8;
            tile[ty + i * 8][tx] = (k < K) ? W[(size_t)k * N + nt + tx] : 0.f;
        }
        __syncthreads();
#pragma unroll
        for (int i = 0; i < 4; i++) {
            int n = nt + ty + i * 8;
            int k = kt + tx;
            float v = tile[tx][ty + i * 8];
            __nv_bfloat16 h = __float2bfloat16(v);
            g_Bh[off + (size_t)n * KP + k] = h;
            g_Bl[off + (size_t)n * KP + k] = __float2bfloat16(v - __bfloat162float(h));
        }
    } else {
        // plain copy: W_txt [300,1024] -> [384,1024] zero-padded
        const float* W = wt;
        const int rows = 300, padRows = 384, cols = 1024;
        int r0 = blockIdx.y * 32, c0 = blockIdx.x * 32;
        if (r0 >= padRows || c0 >= cols) return;
#pragma unroll
        for (int i = 0; i < 4; i++) {
            int r = r0 + ty + i * 8, c = c0 + tx;
            float v = (r < rows) ? W[(size_t)r * cols + c] : 0.f;
            __nv_bfloat16 h = __float2bfloat16(v);
            g_Bh[OFF_TXTP + (size_t)r * cols + c] = h;
            g_Bl[OFF_TXTP + (size_t)r * cols + c] = __float2bfloat16(v - __bfloat162float(h));
        }
    }
}

// fold text fc bias through G0: g_bT = b_txt@G0 (warp per column)
__global__ void k_bias(const float* __restrict__ tb, const float* __restrict__ g0) {
    int gw = (blockIdx.x * blockDim.x + threadIdx.x) >> 5;   // 0..1023
    int lane = threadIdx.x & 31;
    if (gw >= 1024) return;
    float s = 0.f;
#pragma unroll 4
    for (int j = lane; j < 1024; j += 32)
        s += tb[j] * g0[(size_t)j * 1024 + gw];
#pragma unroll
    for (int o = 16; o; o >>= 1) s += __shfl_xor_sync(0xffffffffu, s, o);
    if (lane == 0) g_bT[gw] = s;
}

// ---------------- pipelined mma.sync bf16x3 GEMM ----------------
// cMode: 1 = fp32 -> g_F, 2 = split -> g_Abh/g_Abl (ld 1024), 4 = split -> g_Bh/g_Bl at cOff
// aListSel / outListSel: 0 identity, 1/2 compacted lists, 5 image-node formula
// biasSel: 0 none, 1 g_bT, 3 extBias
#define SROW 40
#define TILEB (128 * SROW * 2)
#define STAGEB (4 * TILEB)
#define SMEM_GEMM (2 * STAGEB)

__global__ __launch_bounds__(256, 2)
void mma_gemm(int nChunks, int KP, size_t bOff,
              int aSel, int cMode, int ldC, size_t cOff,
              int cntSel, int cntImm, int aListSel, int outListSel,
              int biasSel, const float* __restrict__ extBias,
              const float* __restrict__ al, const float* __restrict__ ar,
              int NH, int skipImg) {
    const int* cp = sel_cnt(cntSel);
    int cnt = cp ? *cp : cntImm;
    int row0 = blockIdx.y * 128;
    if (row0 >= cnt) return;
    int col0 = blockIdx.x * 128;

    extern __shared__ char sm[];
    uint32_t sb = smem_u32(sm);

    const __nv_bfloat16* Ah = sel_Ah(aSel);
    const __nv_bfloat16* Al = sel_Al(aSel);
    const __nv_bfloat16* Bh = g_Bh + bOff;
    const __nv_bfloat16* Bl = g_Bl + bOff;
    const int* alist = sel_list(aListSel, nullptr);

    int tid = threadIdx.x, lane = tid & 31, wid = tid >> 5;
    int wm = wid & 1, wn = wid >> 1;

    float acc[4][4][4];
#pragma unroll
    for (int i = 0; i < 4; i++)
#pragma unroll
        for (int j = 0; j < 4; j++)
#pragma unroll
            for (int q = 0; q < 4; q++) acc[i][j][q] = 0.f;

    int lrow = tid >> 2;
    int lk   = (tid & 3) * 8;

    int arow0g = 0, arow1g = 0; int av0 = 0, av1 = 0;
    {
        int r0 = row0 + lrow, r1 = row0 + lrow + 64;
        if (r0 < cnt) {
            av0 = 16;
            arow0g = (aListSel == 5) ? img_row(r0) : (alist ? alist[r0] : r0);
        }
        if (r1 < cnt) {
            av1 = 16;
            arow1g = (aListSel == 5) ? img_row(r1) : (alist ? alist[r1] : r1);
        }
    }
    int brow0 = col0 + lrow, brow1 = col0 + lrow + 64;

#define LOAD_CHUNK(c, s) do {                                                   \
        int k0g = (c) * 32;                                                     \
        uint32_t st = sb + (s) * STAGEB;                                        \
        uint32_t d0 = st + (uint32_t)(lrow * SROW + lk) * 2;                    \
        uint32_t d1 = st + (uint32_t)((lrow + 64) * SROW + lk) * 2;             \
        cpa16(d0,             Ah + (size_t)arow0g * KP + k0g + lk, av0);        \
        cpa16(d1,             Ah + (size_t)arow1g * KP + k0g + lk, av1);        \
        cpa16(d0 + TILEB,     Al + (size_t)arow0g * KP + k0g + lk, av0);        \
        cpa16(d1 + TILEB,     Al + (size_t)arow1g * KP + k0g + lk, av1);        \
        cpa16(d0 + 2 * TILEB, Bh + (size_t)brow0 * KP + k0g + lk, 16);          \
        cpa16(d1 + 2 * TILEB, Bh + (size_t)brow1 * KP + k0g + lk, 16);          \
        cpa16(d0 + 3 * TILEB, Bl + (size_t)brow0 * KP + k0g + lk, 16);          \
        cpa16(d1 + 3 * TILEB, Bl + (size_t)brow1 * KP + k0g + lk, 16);          \
        cpa_commit();                                                           \
    } while (0)

    int aR = (lane & 15), aC = (lane >> 4) << 3;
    int bR = (lane & 7),  bC = ((lane >> 3) & 1) << 3;

    LOAD_CHUNK(0, 0);
    for (int c = 0; c < nChunks; c++) {
        if (c + 1 < nChunks) {
            LOAD_CHUNK(c + 1, (c + 1) & 1);
            cpa_wait<1>();
        } else {
            cpa_wait<0>();
        }
        __syncthreads();
        uint32_t st = sb + (uint32_t)(c & 1) * STAGEB;
#pragma unroll
        for (int ks = 0; ks < 2; ks++) {
            int k0 = ks * 16;
            uint32_t a[4][4], bh[4][2], bl[4][2];
            uint32_t aoff[4];
#pragma unroll
            for (int am = 0; am < 4; am++) {
                aoff[am] = st + (uint32_t)((wm * 64 + am * 16 + aR) * SROW + k0 + aC) * 2;
                ldsm_x4(a[am], aoff[am]);
            }
#pragma unroll
            for (int bn = 0; bn < 4; bn++) {
                uint32_t off = st + (uint32_t)((wn * 32 + bn * 8 + bR) * SROW + k0 + bC) * 2;
                ldsm_x2(bh[bn], off + 2 * TILEB);
                ldsm_x2(bl[bn], off + 3 * TILEB);
            }
#pragma unroll
            for (int am = 0; am < 4; am++)
#pragma unroll
                for (int bn = 0; bn < 4; bn++)
                    mma16816(acc[am][bn], a[am], bh[bn]);
#pragma unroll
            for (int am = 0; am < 4; am++)
#pragma unroll
                for (int bn = 0; bn < 4; bn++)
                    mma16816(acc[am][bn], a[am], bl[bn]);
#pragma unroll
            for (int am = 0; am < 4; am++)
                ldsm_x4(a[am], aoff[am] + TILEB);
#pragma unroll
            for (int am = 0; am < 4; am++)
#pragma unroll
                for (int bn = 0; bn < 4; bn++)
                    mma16816(acc[am][bn], a[am], bh[bn]);
        }
        __syncthreads();
    }
#undef LOAD_CHUNK

    // ---------------- epilogue ----------------
    const int* ol = sel_list(outListSel, nullptr);
    const float* bias = (biasSel == 1) ? g_bT : ((biasSel == 3) ? extBias : nullptr);
    int h = 0;
    if (al) h = (col0 + wn * 32) / (ldC / NH);

#pragma unroll
    for (int am = 0; am < 4; am++) {
#pragma unroll
        for (int part = 0; part < 2; part++) {
            int r = row0 + wm * 64 + am * 16 + (lane >> 2) + part * 8;
            bool valid = r < cnt;
            int orow = 0;
            if (valid) {
                if (outListSel == 5)      orow = img_row(r);
                else if (ol)              orow = ol[r];
                else                      orow = r;
            }
            bool doE = valid && (al != nullptr);
            if (doE && skipImg) {
                int p = orow % PER_;
                if (p >= W_ && p < W_ + I_) doE = false;
            }
            float sl = 0.f, sr = 0.f;
#pragma unroll
            for (int bn = 0; bn < 4; bn++) {
                int cidx = col0 + wn * 32 + bn * 8 + (lane & 3) * 2;
                float x = acc[am][bn][part * 2 + 0];
                float y = acc[am][bn][part * 2 + 1];
                if (bias) { x += bias[cidx]; y += bias[cidx + 1]; }
                if (doE) {
                    sl += x * al[cidx] + y * al[cidx + 1];
                    sr += x * ar[cidx] + y * ar[cidx + 1];
                }
                if (valid) {
                    if (cMode == 1) {
                        float2 v; v.x = x; v.y = y;
                        *(float2*)&g_F[(size_t)orow * ldC + cidx] = v;
                    } else if (cMode == 2) {
                        size_t o = (size_t)orow * 1024 + cidx;
                        __nv_bfloat16 hx = __float2bfloat16(x);
                        __nv_bfloat16 hy = __float2bfloat16(y);
                        __nv_bfloat162 H; H.x = hx; H.y = hy;
                        __nv_bfloat162 L;
                        L.x = __float2bfloat16(x - __bfloat162float(hx));
                        L.y = __float2bfloat16(y - __bfloat162float(hy));
                        *(__nv_bfloat162*)&g_Abh[o] = H;
                        *(__nv_bfloat162*)&g_Abl[o] = L;
                    } else {
                        size_t o = cOff + (size_t)orow * ldC + cidx;
                        __nv_bfloat16 hx = __float2bfloat16(x);
                        __nv_bfloat16 hy = __float2bfloat16(y);
                        __nv_bfloat162 H; H.x = hx; H.y = hy;
                        __nv_bfloat162 L;
                        L.x = __float2bfloat16(x - __bfloat162float(hx));
                        L.y = __float2bfloat16(y - __bfloat162float(hy));
                        *(__nv_bfloat162*)&g_Bh[o] = H;
                        *(__nv_bfloat162*)&g_Bl[o] = L;
                    }
                }
            }
            if (al) {
                sl += __shfl_xor_sync(0xffffffffu, sl, 1);
                sl += __shfl_xor_sync(0xffffffffu, sl, 2);
                sr += __shfl_xor_sync(0xffffffffu, sr, 1);
                sr += __shfl_xor_sync(0xffffffffu, sr, 2);
                if (doE && (lane & 3) == 0) {
                    atomicAdd(&g_EL[orow * NH + h], sl);
                    atomicAdd(&g_ER[orow * NH + h], sr);
                }
            }
        }
    }
}

// ---------------- sets/CSR ----------------
__global__ void k_init() {
    int i = blockIdx.x * blockDim.x + threadIdx.x;
    if (i < NND) {
        g_A1f[i] = 0; g_R1f[i] = 0;
        g_deg[i] = 0;
#pragma unroll
        for (int h = 0; h < 4; h++) { g_EL[i * 4 + h] = 0.f; g_ER[i * 4 + h] = 0.f; }
    }
    if (i == NND) g_deg[NND] = 0;
    if (i == 0) { g_cnt1 = 0; g_cntR = 0; }
}
__global__ void k_markA1(const int* __restrict__ src, const int* __restrict__ dst,
                         const int* __restrict__ sid, int E) {
    int e = blockIdx.x * blockDim.x + threadIdx.x;
    if (e < E) {
        int d = dst[e];
        if (d == sid[0] || d == sid[1] || d == sid[2] || d == sid[3])
            g_A1f[src[e]] = 1;
    }
}
__global__ void k_markR1(const int* __restrict__ src, const int* __restrict__ dst, int E) {
    int e = blockIdx.x * blockDim.x + threadIdx.x;
    if (e < E && g_A1f[dst[e]]) g_R1f[src[e]] = 1;
}
__global__ void k_compact_count(const int* __restrict__ dst, int E) {
    int i = blockIdx.x * blockDim.x + threadIdx.x;
    if (i < NND) {
        if (g_A1f[i]) g_list1[atomicAdd(&g_cnt1, 1)] = i;
        if (g_R1f[i]) g_listR[atomicAdd(&g_cntR, 1)] = i;
    }
    if (i < E) atomicAdd(&g_deg[dst[i]], 1);
}
__global__ void k_scan() {
    __shared__ int sh[1024];
    int tid = threadIdx.x;
    const int chunk = (NND + 1023) >> 10;
    int lo = tid * chunk;
    int hi = lo + chunk; if (hi > NND) hi = NND; if (lo > NND) lo = NND;
    int sum = 0;
    for (int i = lo; i < hi; i++) sum += g_deg[i];
    sh[tid] = sum; __syncthreads();
    for (int d = 1; d < 1024; d <<= 1) {
        int v = 0;
        if (tid >= d) v = sh[tid - d];
        __syncthreads();
        if (tid >= d) sh[tid] += v;
        __syncthreads();
    }
    int run = (tid == 0) ? 0 : sh[tid - 1];
    for (int i = lo; i < hi; i++) {
        g_off[i] = run; g_cur[i] = run; run += g_deg[i];
    }
    if (tid == 1023) g_off[NND] = run;
}
__global__ void k_fill(const int* __restrict__ src, const int* __restrict__ dst, int E) {
    int e = blockIdx.x * blockDim.x + threadIdx.x;
    if (e < E) {
        int p = atomicAdd(&g_cur[dst[e]], 1);
        g_esrc[p] = src[e];
    }
}

__global__ void k_zeroELR(int which, int NH) {
    int n = (which == 1) ? g_cnt1 : g_cntR;
    const int* list = (which == 1) ? g_list1 : g_listR;
    int total = n * NH;
    int stride = gridDim.x * blockDim.x;
    for (int i = blockIdx.x * blockDim.x + threadIdx.x; i < total; i += stride) {
        int nd = list[i / NH];
        int h = i - (i / NH) * NH;
        g_EL[nd * NH + h] = 0.f;
        g_ER[nd * NH + h] = 0.f;
    }
}

// ---------------- GAT attention ----------------
template <int NH, int DD, bool ACT>
__global__ void k_attn(const float* __restrict__ bias, int outMode,
                       int listSel, int cntSel, int cntImm,
                       const int* __restrict__ extList, float* __restrict__ extOut) {
    constexpr int WID = NH * DD;
    constexpr int NE  = WID / 128;
    constexpr int CE  = 128 / NH;
    const int* cp = sel_cnt(cntSel);
    int cnt = cp ? *cp : cntImm;
    const int* list = sel_list(listSel, extList);
    int tid = threadIdx.x;

    __shared__ float s_er[NH], s_m[NH], s_iz[NH];
    __shared__ float red[128];
    __shared__ float swt[32 * NH];
    __shared__ int   ssrc[32];

    for (int bi = blockIdx.x; bi < cnt; bi += gridDim.x) {
        int nd = list ? list[bi] : bi;
        int lo  = g_off[nd];
        int deg = g_off[nd + 1] - lo;

        if (tid < NH) s_er[tid] = g_ER[nd * NH + tid];
        __syncthreads();

        int h  = tid / CE;
        int e0 = tid % CE;
        float erh = s_er[h];

        float lmax = -1e30f;
        for (int e = e0; e < deg; e += CE) {
            int s = g_esrc[lo + e];
            float x = g_EL[s * NH + h] + erh;
            x = x > 0.f ? x : 0.2f * x;
            lmax = fmaxf(lmax, x);
        }
        red[tid] = lmax; __syncthreads();
#pragma unroll
        for (int st = CE / 2; st > 0; st >>= 1) {
            if (e0 < st) red[tid] = fmaxf(red[tid], red[tid + st]);
            __syncthreads();
        }
        if (e0 == 0) s_m[h] = red[tid];
        __syncthreads();
        float mh = s_m[h];

        float lsum = 0.f;
        for (int e = e0; e < deg; e += CE) {
            int s = g_esrc[lo + e];
            float x = g_EL[s * NH + h] + erh;
            x = x > 0.f ? x : 0.2f * x;
            lsum += expf(x - mh);
        }
        red[tid] = lsum; __syncthreads();
#pragma unroll
        for (int st = CE / 2; st > 0; st >>= 1) {
            if (e0 < st) red[tid] += red[tid + st];
            __syncthreads();
        }
        if (e0 == 0) s_iz[h] = 1.f / red[tid];
        __syncthreads();

        float accv[NE];
        int hd[NE];
#pragma unroll
        for (int j = 0; j < NE; j++) { accv[j] = 0.f; hd[j] = (tid + j * 128) / DD; }

        for (int base = 0; base < deg; base += 32) {
            int mcnt = deg - base; if (mcnt > 32) mcnt = 32;
            if (tid < 32 * NH) {
                int eL = tid / NH, hh = tid - (tid / NH) * NH;
                float wv = 0.f;
                if (eL < mcnt) {
                    int s = g_esrc[lo + base + eL];
                    float x = g_EL[s * NH + hh] + s_er[hh];
                    x = x > 0.f ? x : 0.2f * x;
                    wv = expf(x - s_m[hh]) * s_iz[hh];
                    if (hh == 0) ssrc[eL] = s;
                }
                swt[eL * NH + hh] = wv;
            }
            __syncthreads();
            for (int eL = 0; eL < mcnt; eL++) {
                int s = ssrc[eL];
                const float* fr = g_F + (size_t)s * WID;
#pragma unroll
                for (int j = 0; j < NE; j++)
                    accv[j] += swt[eL * NH + hd[j]] * fr[tid + j * 128];
            }
            __syncthreads();
        }

#pragma unroll
        for (int j = 0; j < NE; j++) {
            int c = tid + j * 128;
            float v = accv[j] + bias[c];
            if (ACT) v = v > 0.f ? v : (expf(v) - 1.f);
            if (outMode == 3) {
                extOut[(size_t)bi * WID + c] = v;
            } else {
                __nv_bfloat16* dh = (outMode == 1 ? g_Aah : g_Abh);
                __nv_bfloat16* dl = (outMode == 1 ? g_Aal : g_Abl);
                split_store(dh + (size_t)nd * 1024 + c, dl + (size_t)nd * 1024 + c, v);
            }
        }
    }
}

// ---------------- launch ----------------
extern "C" void kernel_launch(void* const* d_in, const int* in_sizes, int n_in,
                              void* d_out, int out_size) {
    const int*   all_words      = (const int*)  d_in[0];
    const float* image_feats    = (const float*)d_in[1];
    const int*   sentences      = (const int*)  d_in[2];
    const float* sentence_mask  = (const float*)d_in[3];
    const int*   utterances     = (const int*)  d_in[4];
    const float* utterance_mask = (const float*)d_in[5];
    const int*   session_ids    = (const int*)  d_in[6];
    const int*   edge_src       = (const int*)  d_in[7];
    const int*   edge_dst       = (const int*)  d_in[8];
    const float* word_embed     = (const float*)d_in[9];
    const float* text_fc_w      = (const float*)d_in[10];
    const float* text_fc_b      = (const float*)d_in[11];
    const float* image_fc_w     = (const float*)d_in[12];
    const float* image_fc_b     = (const float*)d_in[13];
    const float* gat0_fc = (const float*)d_in[14];
    const float* gat0_al = (const float*)d_in[15];
    const float* gat0_ar = (const float*)d_in[16];
    const float* gat0_b  = (const float*)d_in[17];
    const float* gat1_fc = (const float*)d_in[18];
    const float* gat1_al = (const float*)d_in[19];
    const float* gat1_ar = (const float*)d_in[20];
    const float* gat1_b  = (const float*)d_in[21];
    const float* gat2_fc = (const float*)d_in[22];
    const float* gat2_al = (const float*)d_in[23];
    const float* gat2_ar = (const float*)d_in[24];
    const float* gat2_b  = (const float*)d_in[25];
    float* out = (float*)d_out;
    int E = in_sizes[7];

    cudaFuncSetAttribute(mma_gemm, cudaFuncAttributeMaxDynamicSharedMemorySize, SMEM_GEMM);

    // features + weight prep
    k_feat1<<<NND, 128>>>(all_words, sentences, sentence_mask, word_embed);
    k_feat23<<<BB * (U_ + 1), 128>>>(utterances, utterance_mask);
    k_splitWall<<<dim3(32, 64, 5), dim3(32, 8)>>>(gat0_fc, gat1_fc, gat2_fc,
                                                  text_fc_w, image_fc_w);
    k_bias<<<128, 256>>>(text_fc_b, gat0_fc);
    k_splitImg<<<512, 256>>>(image_feats);

    // sets + CSR (also zeroes EL/ER for layer 0)
    k_init<<<(NND + 256) / 256, 256>>>();
    k_markA1<<<(E + 255) / 256, 256>>>(edge_src, edge_dst, session_ids, E);
    k_markR1<<<(E + 255) / 256, 256>>>(edge_src, edge_dst, E);
    k_compact_count<<<(E + 255) / 256, 256>>>(edge_dst, E);
    k_scan<<<1, 1024>>>();
    k_fill<<<(E + 255) / 256, 256>>>(edge_src, edge_dst, E);

    // precompute fused text weight: (W_txt@G0)^T stored [1024, 384]
    mma_gemm<<<dim3(3, 8), 256, SMEM_GEMM>>>(32, 1024, OFF_TXTP, 4, 4, 384, OFF_TXTF,
                                             0, 1024, 0, 0, 0, nullptr,
                                             nullptr, nullptr, 1, 0);

    // layer-0 f for text-space rows: APa[*,384] @ TXTF -> F (+b_T, +elr, skip img)
    mma_gemm<<<dim3(8, 68), 256, SMEM_GEMM>>>(12, 384, OFF_TXTF, 1, 1, 1024, 0,
                                              0, NND, 0, 0, 1, nullptr,
                                              gat0_al, gat0_ar, 4, 1);
    // image FC: IMG[256,2048] @ Wimg^T -> h_img (+b_img) split into APb image rows
    mma_gemm<<<dim3(8, 2), 256, SMEM_GEMM>>>(64, 2048, OFF_IMGT, 3, 2, 1024, 0,
                                             0, 256, 0, 5, 3, image_fc_b,
                                             nullptr, nullptr, 1, 0);
    // image L0: APb image rows @ G0 -> F image rows (+elr)
    mma_gemm<<<dim3(8, 2), 256, SMEM_GEMM>>>(32, 1024, OFF_G0, 2, 1, 1024, 0,
                                             0, 256, 5, 5, 0, nullptr,
                                             gat0_al, gat0_ar, 4, 0);
    k_attn<4, 256, true><<<2176, 128>>>(gat0_b, 1, 2, 2, 0, nullptr, nullptr);

    // layer 1
    k_zeroELR<<<32, 256>>>(2, 4);
    mma_gemm<<<dim3(8, 68), 256, SMEM_GEMM>>>(32, 1024, OFF_G1, 1, 1, 1024, 0,
                                              2, 0, 2, 2, 0, nullptr,
                                              gat1_al, gat1_ar, 4, 0);
    k_attn<4, 256, true><<<2176, 128>>>(gat1_b, 2, 1, 1, 0, nullptr, nullptr);

    // layer 2
    k_zeroELR<<<32, 256>>>(1, 1);
    mma_gemm<<<dim3(4, 68), 256, SMEM_GEMM>>>(32, 1024, OFF_G2, 2, 1, 512, 0,
                                              1, 0, 1, 1, 0, nullptr,
                                              gat2_al, gat2_ar, 1, 0);
    k_attn<1, 512, false><<<32, 128>>>(gat2_b, 3, 3, 0, BB, session_ids, out);
}

// round 14
// speedup vs baseline: 1.0156x; 1.0156x over previous
#include <cuda_runtime.h>
#include <cuda_bf16.h>
#include <math.h>
#include <stdint.h>

// Problem constants
#define BB   4
#define W_   2000
#define I_   64
#define S_   64
#define T_   24
#define U_   32
#define US_  2
#define PER_ 2161
#define NND  8644
#define EMAX 147456

// weight regions in g_Bh/g_Bl (bf16 element offsets)
#define OFF_G0   0            // G0^T [1024,1024]
#define OFF_G1   1048576      // G1^T [1024,1024]
#define OFF_G2   2097152      // G2^T [512,1024]
#define OFF_TXTP 2621440      // W_txt plain [384(pad300),1024]
#define OFF_IMGP 3014656      // W_img plain [2048,1024]
#define OFF_TXTF 5111808      // fused (W_txt@G0) [1024,384]
#define OFF_IMGF 5505024      // fused (W_img@G0) [1024,2048]
#define BTOT     7602176

// ---------------- scratch (device globals; no allocation) ----------------
__device__ float g_F[(size_t)NND * 1024];
__device__ __nv_bfloat16 g_Aah[(size_t)NND * 1024];  // APa hi
__device__ __nv_bfloat16 g_Aal[(size_t)NND * 1024];  // APa lo
__device__ __nv_bfloat16 g_Abh[(size_t)NND * 1024];  // APb hi
__device__ __nv_bfloat16 g_Abl[(size_t)NND * 1024];  // APb lo
__device__ __nv_bfloat16 g_Imh[256 * 2048];
__device__ __nv_bfloat16 g_Iml[256 * 2048];
__device__ __nv_bfloat16 g_Bh[BTOT];
__device__ __nv_bfloat16 g_Bl[BTOT];
__device__ float g_bT[1024];            // b_txt @ G0
__device__ float g_bI[1024];            // b_img @ G0
__device__ float g_SF[BB * S_ * 300];
__device__ float g_EL[NND * 4];
__device__ float g_ER[NND * 4];
__device__ int   g_deg[NND + 1];
__device__ int   g_off[NND + 1];
__device__ int   g_cur[NND];
__device__ int   g_esrc[EMAX];
__device__ unsigned char g_A1f[NND], g_R1f[NND];
__device__ int   g_list1[NND], g_listR[NND];
__device__ int   g_cnt1, g_cntR;

__device__ __forceinline__ uint32_t smem_u32(const void* p) {
    uint32_t a;
    asm("{ .reg .u64 t; cvta.to.shared.u64 t, %1; cvt.u32.u64 %0, t; }" : "=r"(a) : "l"(p));
    return a;
}

// ---------------- mma.sync / cp.async helpers ----------------
__device__ __forceinline__ void ldsm_x4(uint32_t* r, uint32_t addr) {
    asm volatile("ldmatrix.sync.aligned.m8n8.x4.shared.b16 {%0,%1,%2,%3}, [%4];"
                 : "=r"(r[0]), "=r"(r[1]), "=r"(r[2]), "=r"(r[3]) : "r"(addr));
}
__device__ __forceinline__ void ldsm_x2(uint32_t* r, uint32_t addr) {
    asm volatile("ldmatrix.sync.aligned.m8n8.x2.shared.b16 {%0,%1}, [%2];"
                 : "=r"(r[0]), "=r"(r[1]) : "r"(addr));
}
__device__ __forceinline__ void mma16816(float* c, const uint32_t* a, const uint32_t* b) {
    asm volatile(
        "mma.sync.aligned.m16n8k16.row.col.f32.bf16.bf16.f32 "
        "{%0,%1,%2,%3},{%4,%5,%6,%7},{%8,%9},{%0,%1,%2,%3};"
        : "+f"(c[0]), "+f"(c[1]), "+f"(c[2]), "+f"(c[3])
        : "r"(a[0]), "r"(a[1]), "r"(a[2]), "r"(a[3]), "r"(b[0]), "r"(b[1]));
}
__device__ __forceinline__ void cpa16(uint32_t dst, const void* src, int sz) {
    asm volatile("cp.async.cg.shared.global [%0], [%1], 16, %2;"
                 :: "r"(dst), "l"(src), "r"(sz));
}
__device__ __forceinline__ void cpa_commit() {
    asm volatile("cp.async.commit_group;");
}
template <int N>
__device__ __forceinline__ void cpa_wait() {
    asm volatile("cp.async.wait_group %0;" :: "n"(N));
}

// ---------------- selectors ----------------
__device__ __forceinline__ const __nv_bfloat16* sel_Ah(int s) {
    if (s == 1) return g_Aah;
    if (s == 2) return g_Abh;
    if (s == 3) return g_Imh;
    return g_Bh + OFF_G0;                 // 4: G0^T as A operand
}
__device__ __forceinline__ const __nv_bfloat16* sel_Al(int s) {
    if (s == 1) return g_Aal;
    if (s == 2) return g_Abl;
    if (s == 3) return g_Iml;
    return g_Bl + OFF_G0;
}
__device__ __forceinline__ const int* sel_list(int s, const int* ext) {
    if (s == 1) return g_list1;
    if (s == 2) return g_listR;
    if (s == 3) return ext;
    return nullptr;
}
__device__ __forceinline__ const int* sel_cnt(int s) {
    if (s == 1) return &g_cnt1;
    if (s == 2) return &g_cntR;
    return nullptr;
}
__device__ __forceinline__ int img_row(int r) {
    return (r / I_) * PER_ + W_ + (r % I_);
}

__device__ __forceinline__ void split_store(__nv_bfloat16* ph, __nv_bfloat16* pl, float v) {
    __nv_bfloat16 h = __float2bfloat16(v);
    __nv_bfloat16 l = __float2bfloat16(v - __bfloat162float(h));
    *ph = h; *pl = l;
}

// write a 300-dim feature into APa split (ld=384, zero-padded)
__device__ __forceinline__ void feat_out(int node, int tid, float v0, float v1, float v2) {
    size_t base = (size_t)node * 384;
    split_store(g_Aah + base + tid, g_Aal + base + tid, v0);
    split_store(g_Aah + base + tid + 128, g_Aal + base + tid + 128, v1);
    int d2 = tid + 256;
    if (d2 < 300) {
        split_store(g_Aah + base + d2, g_Aal + base + d2, v2);
    } else {
        g_Aah[base + d2] = __float2bfloat16(0.f);
        g_Aal[base + d2] = __float2bfloat16(0.f);
    }
}

// ---------------- staged feature kernels ----------------
__global__ void k_feat1(const int* __restrict__ aw,
                        const int* __restrict__ sent, const float* __restrict__ smask,
                        const float* __restrict__ we) {
    int node = blockIdx.x;
    int b = node / PER_, p = node - b * PER_;
    int tid = threadIdx.x;
    float v0 = 0.f, v1 = 0.f, v2 = 0.f;

    if (p < W_) {
        const float* row = we + (size_t)aw[(size_t)b * W_ + p] * 300;
        v0 = row[tid]; v1 = row[tid + 128];
        if (tid < 44) v2 = row[tid + 256];
    } else if (p >= W_ + I_ && p < W_ + I_ + S_) {
        int s = p - (W_ + I_);
        const int*   sw = sent + ((size_t)b * S_ + s) * T_;
        const float* mk = smask + ((size_t)b * S_ + s) * T_;
        float c = 0.f, a0 = 0.f, a1 = 0.f, a2 = 0.f;
#pragma unroll 4
        for (int t = 0; t < T_; t++) {
            float m = mk[t]; c += m;
            const float* row = we + (size_t)sw[t] * 300;
            a0 += m * row[tid];
            a1 += m * row[tid + 128];
            if (tid < 44) a2 += m * row[tid + 256];
        }
        float inv = 1.f / (c == 0.f ? 1.f : c);
        v0 = a0 * inv; v1 = a1 * inv; v2 = a2 * inv;
        float* sf = g_SF + ((size_t)b * S_ + s) * 300;
        sf[tid] = v0; sf[tid + 128] = v1;
        if (tid < 44) sf[tid + 256] = v2;
    } else if (p >= W_ + I_ + S_) {
        return;
    }
    feat_out(node, tid, v0, v1, v2);
}

__device__ __forceinline__ void utt_from_cache(const int* __restrict__ utts,
                                               const float* __restrict__ umask,
                                               int b, int u, int tid,
                                               float& o0, float& o1, float& o2) {
    float c = 0.f, a0 = 0.f, a1 = 0.f, a2 = 0.f;
#pragma unroll
    for (int t = 0; t < US_; t++) {
        size_t e = ((size_t)b * U_ + u) * US_ + t;
        float m = umask[e]; c += m;
        const float* sf = g_SF + ((size_t)b * S_ + utts[e]) * 300;
        a0 += m * sf[tid];
        a1 += m * sf[tid + 128];
        if (tid < 44) a2 += m * sf[tid + 256];
    }
    float inv = 1.f / (c == 0.f ? 1.f : c);
    o0 = a0 * inv; o1 = a1 * inv; o2 = a2 * inv;
}

__global__ void k_feat23(const int* __restrict__ utts, const float* __restrict__ umask) {
    int i = blockIdx.x;
    int b = i / (U_ + 1), q = i - b * (U_ + 1);
    int tid = threadIdx.x;
    if (q < U_) {
        float v0, v1, v2;
        utt_from_cache(utts, umask, b, q, tid, v0, v1, v2);
        feat_out(b * PER_ + W_ + I_ + S_ + q, tid, v0, v1, v2);
    } else {
        float a0 = 0.f, a1 = 0.f, a2 = 0.f;
        for (int u = 0; u < U_; u++) {
            float t0, t1, t2;
            utt_from_cache(utts, umask, b, u, tid, t0, t1, t2);
            a0 += t0; a1 += t1; a2 += t2;
        }
        const float inv = 1.f / (float)U_;
        feat_out(b * PER_ + W_ + I_ + S_ + U_, tid, a0 * inv, a1 * inv, a2 * inv);
    }
}

// ---------------- image feats split ----------------
__global__ void k_splitImg(const float* __restrict__ A) {
    long total = 256L * 2048 / 4;
    long stride = (long)gridDim.x * blockDim.x;
    for (long i = (long)blockIdx.x * blockDim.x + threadIdx.x; i < total; i += stride) {
        long e = i * 4;
        float4 v = *(const float4*)(A + e);
        __nv_bfloat16 h0 = __float2bfloat16(v.x), h1 = __float2bfloat16(v.y);
        __nv_bfloat16 h2 = __float2bfloat16(v.z), h3 = __float2bfloat16(v.w);
        g_Imh[e] = h0; g_Imh[e+1] = h1; g_Imh[e+2] = h2; g_Imh[e+3] = h3;
        g_Iml[e]   = __float2bfloat16(v.x - __bfloat162float(h0));
        g_Iml[e+1] = __float2bfloat16(v.y - __bfloat162float(h1));
        g_Iml[e+2] = __float2bfloat16(v.z - __bfloat162float(h2));
        g_Iml[e+3] = __float2bfloat16(v.w - __bfloat162float(h3));
    }
}

// ---------------- weight splits: 3 transposed + 2 plain ----------------
__global__ void k_splitWall(const float* __restrict__ g0, const float* __restrict__ g1,
                            const float* __restrict__ g2, const float* __restrict__ wt,
                            const float* __restrict__ wi) {
    int z = blockIdx.z;
    int tx = threadIdx.x, ty = threadIdx.y;
    if (z < 3) {
        const float* W; int N; size_t off;
        if (z == 0)      { W = g0; N = 1024; off = OFF_G0; }
        else if (z == 1) { W = g1; N = 1024; off = OFF_G1; }
        else             { W = g2; N = 512;  off = OFF_G2; }
        const int K = 1024, KP = 1024;
        int nt = blockIdx.x * 32, kt = blockIdx.y * 32;
        if (nt >= N || kt >= KP) return;
        __shared__ float tile[32][33];
#pragma unroll
        for (int i = 0; i < 4; i++) {
            int k = kt + ty + i * 8;
            tile[ty + i * 8][tx] = (k < K) ? W[(size_t)k * N + nt + tx] : 0.f;
        }
        __syncthreads();
#pragma unroll
        for (int i = 0; i < 4; i++) {
            int n = nt + ty + i * 8;
            int k = kt + tx;
            float v = tile[tx][ty + i * 8];
            __nv_bfloat16 h = __float2bfloat16(v);
            g_Bh[off + (size_t)n * KP + k] = h;
            g_Bl[off + (size_t)n * KP + k] = __float2bfloat16(v - __bfloat162float(h));
        }
    } else {
        const float* W; int rows, padRows; size_t off;
        if (z == 3) { W = wt; rows = 300;  padRows = 384;  off = OFF_TXTP; }
        else        { W = wi; rows = 2048; padRows = 2048; off = OFF_IMGP; }
        const int cols = 1024;
        int r0 = blockIdx.y * 32, c0 = blockIdx.x * 32;
        if (r0 >= padRows || c0 >= cols) return;
#pragma unroll
        for (int i = 0; i < 4; i++) {
            int r = r0 + ty + i * 8, c = c0 + tx;
            float v = (r < rows) ? W[(size_t)r * cols + c] : 0.f;
            __nv_bfloat16 h = __float2bfloat16(v);
            g_Bh[off + (size_t)r * cols + c] = h;
            g_Bl[off + (size_t)r * cols + c] = __float2bfloat16(v - __bfloat162float(h));
        }
    }
}

// fold fc biases through G0: g_bT = b_txt@G0, g_bI = b_img@G0 (warp per column)
__global__ void k_bias(const float* __restrict__ tb, const float* __restrict__ ib,
                       const float* __restrict__ g0) {
    int gw = (blockIdx.x * blockDim.x + threadIdx.x) >> 5;   // 0..2047
    int lane = threadIdx.x & 31;
    if (gw >= 2048) return;
    int col = gw & 1023;
    const float* bv = (gw < 1024) ? tb : ib;
    float s = 0.f;
#pragma unroll 4
    for (int j = lane; j < 1024; j += 32)
        s += bv[j] * g0[(size_t)j * 1024 + col];
#pragma unroll
    for (int o = 16; o; o >>= 1) s += __shfl_xor_sync(0xffffffffu, s, o);
    if (lane == 0) { if (gw < 1024) g_bT[col] = s; else g_bI[col] = s; }
}

// ---------------- pipelined mma.sync bf16x3 GEMM ----------------
#define SROW 40
#define TILEB (128 * SROW * 2)
#define STAGEB (4 * TILEB)
#define SMEM_GEMM (2 * STAGEB)

__global__ __launch_bounds__(256, 2)
void mma_gemm(int nChunks, int KP, size_t bOff,
              int aSel, int cMode, int ldC, size_t cOff,
              int cntSel, int cntImm, int aListSel, int outListSel,
              int biasSel, const float* __restrict__ al, const float* __restrict__ ar,
              int NH, int skipImg) {
    const int* cp = sel_cnt(cntSel);
    int cnt = cp ? *cp : cntImm;
    int row0 = blockIdx.y * 128;
    if (row0 >= cnt) return;
    int col0 = blockIdx.x * 128;

    extern __shared__ char sm[];
    uint32_t sb = smem_u32(sm);

    const __nv_bfloat16* Ah = sel_Ah(aSel);
    const __nv_bfloat16* Al = sel_Al(aSel);
    const __nv_bfloat16* Bh = g_Bh + bOff;
    const __nv_bfloat16* Bl = g_Bl + bOff;
    const int* alist = sel_list(aListSel, nullptr);

    int tid = threadIdx.x, lane = tid & 31, wid = tid >> 5;
    int wm = wid & 1, wn = wid >> 1;

    float acc[4][4][4];
#pragma unroll
    for (int i = 0; i < 4; i++)
#pragma unroll
        for (int j = 0; j < 4; j++)
#pragma unroll
            for (int q = 0; q < 4; q++) acc[i][j][q] = 0.f;

    int lrow = tid >> 2;
    int lk   = (tid & 3) * 8;

    int arow0g = 0, arow1g = 0; int av0 = 0, av1 = 0;
    {
        int r0 = row0 + lrow, r1 = row0 + lrow + 64;
        if (r0 < cnt) {
            av0 = 16;
            arow0g = (aListSel == 5) ? img_row(r0) : (alist ? alist[r0] : r0);
        }
        if (r1 < cnt) {
            av1 = 16;
            arow1g = (aListSel == 5) ? img_row(r1) : (alist ? alist[r1] : r1);
        }
    }
    int brow0 = col0 + lrow, brow1 = col0 + lrow + 64;

#define LOAD_CHUNK(c, s) do {                                                   \
        int k0g = (c) * 32;                                                     \
        uint32_t st = sb + (s) * STAGEB;                                        \
        uint32_t d0 = st + (uint32_t)(lrow * SROW + lk) * 2;                    \
        uint32_t d1 = st + (uint32_t)((lrow + 64) * SROW + lk) * 2;             \
        cpa16(d0,             Ah + (size_t)arow0g * KP + k0g + lk, av0);        \
        cpa16(d1,             Ah + (size_t)arow1g * KP + k0g + lk, av1);        \
        cpa16(d0 + TILEB,     Al + (size_t)arow0g * KP + k0g + lk, av0);        \
        cpa16(d1 + TILEB,     Al + (size_t)arow1g * KP + k0g + lk, av1);        \
        cpa16(d0 + 2 * TILEB, Bh + (size_t)brow0 * KP + k0g + lk, 16);          \
        cpa16(d1 + 2 * TILEB, Bh + (size_t)brow1 * KP + k0g + lk, 16);          \
        cpa16(d0 + 3 * TILEB, Bl + (size_t)brow0 * KP + k0g + lk, 16);          \
        cpa16(d1 + 3 * TILEB, Bl + (size_t)brow1 * KP + k0g + lk, 16);          \
        cpa_commit();                                                           \
    } while (0)

    int aR = (lane & 15), aC = (lane >> 4) << 3;
    int bR = (lane & 7),  bC = ((lane >> 3) & 1) << 3;

    LOAD_CHUNK(0, 0);
    for (int c = 0; c < nChunks; c++) {
        if (c + 1 < nChunks) {
            LOAD_CHUNK(c + 1, (c + 1) & 1);
            cpa_wait<1>();
        } else {
            cpa_wait<0>();
        }
        __syncthreads();
        uint32_t st = sb + (uint32_t)(c & 1) * STAGEB;
#pragma unroll
        for (int ks = 0; ks < 2; ks++) {
            int k0 = ks * 16;
            uint32_t a[4][4], bh[4][2], bl[4][2];
            uint32_t aoff[4];
#pragma unroll
            for (int am = 0; am < 4; am++) {
                aoff[am] = st + (uint32_t)((wm * 64 + am * 16 + aR) * SROW + k0 + aC) * 2;
                ldsm_x4(a[am], aoff[am]);
            }
#pragma unroll
            for (int bn = 0; bn < 4; bn++) {
                uint32_t off = st + (uint32_t)((wn * 32 + bn * 8 + bR) * SROW + k0 + bC) * 2;
                ldsm_x2(bh[bn], off + 2 * TILEB);
                ldsm_x2(bl[bn], off + 3 * TILEB);
            }
#pragma unroll
            for (int am = 0; am < 4; am++)
#pragma unroll
                for (int bn = 0; bn < 4; bn++)
                    mma16816(acc[am][bn], a[am], bh[bn]);
#pragma unroll
            for (int am = 0; am < 4; am++)
#pragma unroll
                for (int bn = 0; bn < 4; bn++)
                    mma16816(acc[am][bn], a[am], bl[bn]);
#pragma unroll
            for (int am = 0; am < 4; am++)
                ldsm_x4(a[am], aoff[am] + TILEB);
#pragma unroll
            for (int am = 0; am < 4; am++)
#pragma unroll
                for (int bn = 0; bn < 4; bn++)
                    mma16816(acc[am][bn], a[am], bh[bn]);
        }
        __syncthreads();
    }
#undef LOAD_CHUNK

    // ---------------- epilogue ----------------
    const int* ol = sel_list(outListSel, nullptr);
    const float* bias = (biasSel == 1) ? g_bT : ((biasSel == 2) ? g_bI : nullptr);
    int h = 0;
    if (al) h = (col0 + wn * 32) / (ldC / NH);

#pragma unroll
    for (int am = 0; am < 4; am++) {
#pragma unroll
        for (int part = 0; part < 2; part++) {
            int r = row0 + wm * 64 + am * 16 + (lane >> 2) + part * 8;
            bool valid = r < cnt;
            int orow = 0;
            if (valid) {
                if (outListSel == 5)      orow = img_row(r);
                else if (ol)              orow = ol[r];
                else                      orow = r;
            }
            bool doE = valid && (al != nullptr);
            if (doE && skipImg) {
                int p = orow % PER_;
                if (p >= W_ && p < W_ + I_) doE = false;
            }
            float sl = 0.f, sr = 0.f;
#pragma unroll
            for (int bn = 0; bn < 4; bn++) {
                int cidx = col0 + wn * 32 + bn * 8 + (lane & 3) * 2;
                float x = acc[am][bn][part * 2 + 0];
                float y = acc[am][bn][part * 2 + 1];
                if (bias) { x += bias[cidx]; y += bias[cidx + 1]; }
                if (doE) {
                    sl += x * al[cidx] + y * al[cidx + 1];
                    sr += x * ar[cidx] + y * ar[cidx + 1];
                }
                if (valid) {
                    if (cMode == 1) {
                        float2 v; v.x = x; v.y = y;
                        *(float2*)&g_F[(size_t)orow * ldC + cidx] = v;
                    } else if (cMode == 2) {
                        size_t o = (size_t)orow * 1024 + cidx;
                        __nv_bfloat16 hx = __float2bfloat16(x);
                        __nv_bfloat16 hy = __float2bfloat16(y);
                        __nv_bfloat162 H; H.x = hx; H.y = hy;
                        __nv_bfloat162 L;
                        L.x = __float2bfloat16(x - __bfloat162float(hx));
                        L.y = __float2bfloat16(y - __bfloat162float(hy));
                        *(__nv_bfloat162*)&g_Abh[o] = H;
                        *(__nv_bfloat162*)&g_Abl[o] = L;
                    } else {
                        size_t o = cOff + (size_t)orow * ldC + cidx;
                        __nv_bfloat16 hx = __float2bfloat16(x);
                        __nv_bfloat16 hy = __float2bfloat16(y);
                        __nv_bfloat162 H; H.x = hx; H.y = hy;
                        __nv_bfloat162 L;
                        L.x = __float2bfloat16(x - __bfloat162float(hx));
                        L.y = __float2bfloat16(y - __bfloat162float(hy));
                        *(__nv_bfloat162*)&g_Bh[o] = H;
                        *(__nv_bfloat162*)&g_Bl[o] = L;
                    }
                }
            }
            if (al) {
                sl += __shfl_xor_sync(0xffffffffu, sl, 1);
                sl += __shfl_xor_sync(0xffffffffu, sl, 2);
                sr += __shfl_xor_sync(0xffffffffu, sr, 1);
                sr += __shfl_xor_sync(0xffffffffu, sr, 2);
                if (doE && (lane & 3) == 0) {
                    atomicAdd(&g_EL[orow * NH + h], sl);
                    atomicAdd(&g_ER[orow * NH + h], sr);
                }
            }
        }
    }
}

// ---------------- sets/CSR ----------------
__global__ void k_init() {
    int i = blockIdx.x * blockDim.x + threadIdx.x;
    if (i < NND) {
        g_A1f[i] = 0; g_R1f[i] = 0;
        g_deg[i] = 0;
#pragma unroll
        for (int h = 0; h < 4; h++) { g_EL[i * 4 + h] = 0.f; g_ER[i * 4 + h] = 0.f; }
    }
    if (i == NND) g_deg[NND] = 0;
    if (i == 0) { g_cnt1 = 0; g_cntR = 0; }
}
__global__ void k_markA1(const int* __restrict__ src, const int* __restrict__ dst,
                         const int* __restrict__ sid, int E) {
    int e = blockIdx.x * blockDim.x + threadIdx.x;
    if (e < E) {
        int d = dst[e];
        if (d == sid[0] || d == sid[1] || d == sid[2] || d == sid[3])
            g_A1f[src[e]] = 1;
    }
}
__global__ void k_markR1(const int* __restrict__ src, const int* __restrict__ dst, int E) {
    int e = blockIdx.x * blockDim.x + threadIdx.x;
    if (e < E && g_A1f[dst[e]]) g_R1f[src[e]] = 1;
}
__global__ void k_compact_count(const int* __restrict__ dst, int E) {
    int i = blockIdx.x * blockDim.x + threadIdx.x;
    if (i < NND) {
        if (g_A1f[i]) g_list1[atomicAdd(&g_cnt1, 1)] = i;
        if (g_R1f[i]) g_listR[atomicAdd(&g_cntR, 1)] = i;
    }
    if (i < E) atomicAdd(&g_deg[dst[i]], 1);
}
__global__ void k_scan() {
    __shared__ int sh[1024];
    int tid = threadIdx.x;
    const int chunk = (NND + 1023) >> 10;
    int lo = tid * chunk;
    int hi = lo + chunk; if (hi > NND) hi = NND; if (lo > NND) lo = NND;
    int sum = 0;
    for (int i = lo; i < hi; i++) sum += g_deg[i];
    sh[tid] = sum; __syncthreads();
    for (int d = 1; d < 1024; d <<= 1) {
        int v = 0;
        if (tid >= d) v = sh[tid - d];
        __syncthreads();
        if (tid >= d) sh[tid] += v;
        __syncthreads();
    }
    int run = (tid == 0) ? 0 : sh[tid - 1];
    for (int i = lo; i < hi; i++) {
        g_off[i] = run; g_cur[i] = run; run += g_deg[i];
    }
    if (tid == 1023) g_off[NND] = run;
}
__global__ void k_fill(const int* __restrict__ src, const int* __restrict__ dst, int E) {
    int e = blockIdx.x * blockDim.x + threadIdx.x;
    if (e < E) {
        int p = atomicAdd(&g_cur[dst[e]], 1);
        g_esrc[p] = src[e];
    }
}

__global__ void k_zeroELR(int which, int NH) {
    int n = (which == 1) ? g_cnt1 : g_cntR;
    const int* list = (which == 1) ? g_list1 : g_listR;
    int total = n * NH;
    int stride = gridDim.x * blockDim.x;
    for (int i = blockIdx.x * blockDim.x + threadIdx.x; i < total; i += stride) {
        int nd = list[i / NH];
        int h = i - (i / NH) * NH;
        g_EL[nd * NH + h] = 0.f;
        g_ER[nd * NH + h] = 0.f;
    }
}

// ---------------- GAT attention ----------------
template <int NH, int DD, bool ACT>
__global__ void k_attn(const float* __restrict__ bias, int outMode,
                       int listSel, int cntSel, int cntImm,
                       const int* __restrict__ extList, float* __restrict__ extOut) {
    constexpr int WID = NH * DD;
    constexpr int NE  = WID / 128;
    constexpr int CE  = 128 / NH;
    const int* cp = sel_cnt(cntSel);
    int cnt = cp ? *cp : cntImm;
    const int* list = sel_list(listSel, extList);
    int tid = threadIdx.x;

    __shared__ float s_er[NH], s_m[NH], s_iz[NH];
    __shared__ float red[128];
    __shared__ float swt[32 * NH];
    __shared__ int   ssrc[32];

    for (int bi = blockIdx.x; bi < cnt; bi += gridDim.x) {
        int nd = list ? list[bi] : bi;
        int lo  = g_off[nd];
        int deg = g_off[nd + 1] - lo;

        if (tid < NH) s_er[tid] = g_ER[nd * NH + tid];
        __syncthreads();

        int h  = tid / CE;
        int e0 = tid % CE;
        float erh = s_er[h];

        float lmax = -1e30f;
        for (int e = e0; e < deg; e += CE) {
            int s = g_esrc[lo + e];
            float x = g_EL[s * NH + h] + erh;
            x = x > 0.f ? x : 0.2f * x;
            lmax = fmaxf(lmax, x);
        }
        red[tid] = lmax; __syncthreads();
#pragma unroll
        for (int st = CE / 2; st > 0; st >>= 1) {
            if (e0 < st) red[tid] = fmaxf(red[tid], red[tid + st]);
            __syncthreads();
        }
        if (e0 == 0) s_m[h] = red[tid];
        __syncthreads();
        float mh = s_m[h];

        float lsum = 0.f;
        for (int e = e0; e < deg; e += CE) {
            int s = g_esrc[lo + e];
            float x = g_EL[s * NH + h] + erh;
            x = x > 0.f ? x : 0.2f * x;
            lsum += expf(x - mh);
        }
        red[tid] = lsum; __syncthreads();
#pragma unroll
        for (int st = CE / 2; st > 0; st >>= 1) {
            if (e0 < st) red[tid] += red[tid + st];
            __syncthreads();
        }
        if (e0 == 0) s_iz[h] = 1.f / red[tid];
        __syncthreads();

        float accv[NE];
        int hd[NE];
#pragma unroll
        for (int j = 0; j < NE; j++) { accv[j] = 0.f; hd[j] = (tid + j * 128) / DD; }

        for (int base = 0; base < deg; base += 32) {
            int mcnt = deg - base; if (mcnt > 32) mcnt = 32;
            if (tid < 32 * NH) {
                int eL = tid / NH, hh = tid - (tid / NH) * NH;
                float wv = 0.f;
                if (eL < mcnt) {
                    int s = g_esrc[lo + base + eL];
                    float x = g_EL[s * NH + hh] + s_er[hh];
                    x = x > 0.f ? x : 0.2f * x;
                    wv = expf(x - s_m[hh]) * s_iz[hh];
                    if (hh == 0) ssrc[eL] = s;
                }
                swt[eL * NH + hh] = wv;
            }
            __syncthreads();
            for (int eL = 0; eL < mcnt; eL++) {
                int s = ssrc[eL];
                const float* fr = g_F + (size_t)s * WID;
#pragma unroll
                for (int j = 0; j < NE; j++)
                    accv[j] += swt[eL * NH + hd[j]] * fr[tid + j * 128];
            }
            __syncthreads();
        }

#pragma unroll
        for (int j = 0; j < NE; j++) {
            int c = tid + j * 128;
            float v = accv[j] + bias[c];
            if (ACT) v = v > 0.f ? v : (expf(v) - 1.f);
            if (outMode == 3) {
                extOut[(size_t)bi * WID + c] = v;
            } else {
                __nv_bfloat16* dh = (outMode == 1 ? g_Aah : g_Abh);
                __nv_bfloat16* dl = (outMode == 1 ? g_Aal : g_Abl);
                split_store(dh + (size_t)nd * 1024 + c, dl + (size_t)nd * 1024 + c, v);
            }
        }
    }
}

// ---------------- launch ----------------
extern "C" void kernel_launch(void* const* d_in, const int* in_sizes, int n_in,
                              void* d_out, int out_size) {
    const int*   all_words      = (const int*)  d_in[0];
    const float* image_feats    = (const float*)d_in[1];
    const int*   sentences      = (const int*)  d_in[2];
    const float* sentence_mask  = (const float*)d_in[3];
    const int*   utterances     = (const int*)  d_in[4];
    const float* utterance_mask = (const float*)d_in[5];
    const int*   session_ids    = (const int*)  d_in[6];
    const int*   edge_src       = (const int*)  d_in[7];
    const int*   edge_dst       = (const int*)  d_in[8];
    const float* word_embed     = (const float*)d_in[9];
    const float* text_fc_w      = (const float*)d_in[10];
    const float* text_fc_b      = (const float*)d_in[11];
    const float* image_fc_w     = (const float*)d_in[12];
    const float* image_fc_b     = (const float*)d_in[13];
    const float* gat0_fc = (const float*)d_in[14];
    const float* gat0_al = (const float*)d_in[15];
    const float* gat0_ar = (const float*)d_in[16];
    const float* gat0_b  = (const float*)d_in[17];
    const float* gat1_fc = (const float*)d_in[18];
    const float* gat1_al = (const float*)d_in[19];
    const float* gat1_ar = (const float*)d_in[20];
    const float* gat1_b  = (const float*)d_in[21];
    const float* gat2_fc = (const float*)d_in[22];
    const float* gat2_al = (const float*)d_in[23];
    const float* gat2_ar = (const float*)d_in[24];
    const float* gat2_b  = (const float*)d_in[25];
    float* out = (float*)d_out;
    int E = in_sizes[7];

    cudaFuncSetAttribute(mma_gemm, cudaFuncAttributeMaxDynamicSharedMemorySize, SMEM_GEMM);

    // features + weight prep
    k_feat1<<<NND, 128>>>(all_words, sentences, sentence_mask, word_embed);
    k_feat23<<<BB * (U_ + 1), 128>>>(utterances, utterance_mask);
    k_splitWall<<<dim3(32, 64, 5), dim3(32, 8)>>>(gat0_fc, gat1_fc, gat2_fc,
                                                  text_fc_w, image_fc_w);
    k_bias<<<256, 256>>>(text_fc_b, image_fc_b, gat0_fc);
    k_splitImg<<<512, 256>>>(image_feats);

    // sets + CSR (also zeroes EL/ER for layer 0)
    k_init<<<(NND + 256) / 256, 256>>>();
    k_markA1<<<(E + 255) / 256, 256>>>(edge_src, edge_dst, session_ids, E);
    k_markR1<<<(E + 255) / 256, 256>>>(edge_src, edge_dst, E);
    k_compact_count<<<(E + 255) / 256, 256>>>(edge_dst, E);
    k_scan<<<1, 1024>>>();
    k_fill<<<(E + 255) / 256, 256>>>(edge_src, edge_dst, E);

    // precompute fused weights: (W_txt@G0) and (W_img@G0), stored [N=1024, K]
    mma_gemm<<<dim3(3, 8), 256, SMEM_GEMM>>>(32, 1024, OFF_TXTP, 4, 4, 384, OFF_TXTF,
                                             0, 1024, 0, 0, 0, nullptr, nullptr, 1, 0);
    mma_gemm<<<dim3(16, 8), 256, SMEM_GEMM>>>(32, 1024, OFF_IMGP, 4, 4, 2048, OFF_IMGF,
                                              0, 1024, 0, 0, 0, nullptr, nullptr, 1, 0);

    // layer-0 f (fused): text rows -> F (+elr, skip image rows), then image rows
    mma_gemm<<<dim3(8, 68), 256, SMEM_GEMM>>>(12, 384, OFF_TXTF, 1, 1, 1024, 0,
                                              0, NND, 0, 0, 1, gat0_al, gat0_ar, 4, 1);
    mma_gemm<<<dim3(8, 2), 256, SMEM_GEMM>>>(64, 2048, OFF_IMGF, 3, 1, 1024, 0,
                                             0, 256, 0, 5, 2, gat0_al, gat0_ar, 4, 0);
    k_attn<4, 256, true><<<2176, 128>>>(gat0_b, 1, 2, 2, 0, nullptr, nullptr);

    // layer 1
    k_zeroELR<<<32, 256>>>(2, 4);
    mma_gemm<<<dim3(8, 68), 256, SMEM_GEMM>>>(32, 1024, OFF_G1, 1, 1, 1024, 0,
                                              2, 0, 2, 2, 0, gat1_al, gat1_ar, 4, 0);
    k_attn<4, 256, true><<<2176, 128>>>(gat1_b, 2, 1, 1, 0, nullptr, nullptr);

    // layer 2
    k_zeroELR<<<32, 256>>>(1, 1);
    mma_gemm<<<dim3(4, 68), 256, SMEM_GEMM>>>(32, 1024, OFF_G2, 2, 1, 512, 0,
                                              1, 0, 1, 1, 0, gat2_al, gat2_ar, 1, 0);
    k_attn<1, 512, false><<<32, 128>>>(gat2_b, 3, 3, 0, BB, session_ids, out);
}

// round 15
// speedup vs baseline: 1.0182x; 1.0026x over previous
#include <cuda_runtime.h>
#include <cuda_bf16.h>
#include <math.h>
#include <stdint.h>

// Problem constants
#define BB   4
#define W_   2000
#define I_   64
#define S_   64
#define T_   24
#define U_   32
#define US_  2
#define PER_ 2161
#define NND  8644
#define EMAX 147456

// weight regions in g_Bh/g_Bl (bf16 element offsets)
#define OFF_G0   0            // G0^T [1024,1024]
#define OFF_G1   1048576      // G1^T [1024,1024]
#define OFF_G2   2097152      // G2^T [512,1024]
#define OFF_TXTP 2621440      // W_txt plain [384(pad300),1024]
#define OFF_IMGP 3014656      // W_img plain [2048,1024]
#define OFF_TXTF 5111808      // fused (W_txt@G0) [1024,384]
#define OFF_IMGF 5505024      // fused (W_img@G0) [1024,2048]
#define BTOT     7602176

// ---------------- scratch (device globals; no allocation) ----------------
__device__ float g_F[(size_t)NND * 1024];
__device__ __nv_bfloat16 g_Aah[(size_t)NND * 1024];  // APa hi
__device__ __nv_bfloat16 g_Aal[(size_t)NND * 1024];  // APa lo
__device__ __nv_bfloat16 g_Abh[(size_t)NND * 1024];  // APb hi
__device__ __nv_bfloat16 g_Abl[(size_t)NND * 1024];  // APb lo
__device__ __nv_bfloat16 g_Imh[256 * 2048];
__device__ __nv_bfloat16 g_Iml[256 * 2048];
__device__ __nv_bfloat16 g_Bh[BTOT];
__device__ __nv_bfloat16 g_Bl[BTOT];
__device__ float g_bT[1024];            // b_txt @ G0
__device__ float g_bI[1024];            // b_img @ G0
__device__ float g_SF[BB * S_ * 300];
__device__ float g_EL[NND * 4];
__device__ float g_ER[NND * 4];
__device__ int   g_deg[NND + 1];
__device__ int   g_off[NND + 1];
__device__ int   g_cur[NND];
__device__ int   g_esrc[EMAX];
__device__ unsigned char g_A1f[NND], g_R1f[NND];
__device__ int   g_list1[NND], g_listR[NND];
__device__ int   g_cnt1, g_cntR;

__device__ __forceinline__ uint32_t smem_u32(const void* p) {
    uint32_t a;
    asm("{ .reg .u64 t; cvta.to.shared.u64 t, %1; cvt.u32.u64 %0, t; }" : "=r"(a) : "l"(p));
    return a;
}

// ---------------- mma.sync / cp.async helpers ----------------
__device__ __forceinline__ void ldsm_x4(uint32_t* r, uint32_t addr) {
    asm volatile("ldmatrix.sync.aligned.m8n8.x4.shared.b16 {%0,%1,%2,%3}, [%4];"
                 : "=r"(r[0]), "=r"(r[1]), "=r"(r[2]), "=r"(r[3]) : "r"(addr));
}
__device__ __forceinline__ void ldsm_x2(uint32_t* r, uint32_t addr) {
    asm volatile("ldmatrix.sync.aligned.m8n8.x2.shared.b16 {%0,%1}, [%2];"
                 : "=r"(r[0]), "=r"(r[1]) : "r"(addr));
}
__device__ __forceinline__ void mma16816(float* c, const uint32_t* a, const uint32_t* b) {
    asm volatile(
        "mma.sync.aligned.m16n8k16.row.col.f32.bf16.bf16.f32 "
        "{%0,%1,%2,%3},{%4,%5,%6,%7},{%8,%9},{%0,%1,%2,%3};"
        : "+f"(c[0]), "+f"(c[1]), "+f"(c[2]), "+f"(c[3])
        : "r"(a[0]), "r"(a[1]), "r"(a[2]), "r"(a[3]), "r"(b[0]), "r"(b[1]));
}
__device__ __forceinline__ void cpa16(uint32_t dst, const void* src, int sz) {
    asm volatile("cp.async.cg.shared.global [%0], [%1], 16, %2;"
                 :: "r"(dst), "l"(src), "r"(sz));
}
__device__ __forceinline__ void cpa_commit() {
    asm volatile("cp.async.commit_group;");
}
template <int N>
__device__ __forceinline__ void cpa_wait() {
    asm volatile("cp.async.wait_group %0;" :: "n"(N));
}

// ---------------- selectors ----------------
__device__ __forceinline__ const __nv_bfloat16* sel_Ah(int s) {
    if (s == 1) return g_Aah;
    if (s == 2) return g_Abh;
    if (s == 3) return g_Imh;
    return g_Bh + OFF_G0;                 // 4: G0^T as A operand
}
__device__ __forceinline__ const __nv_bfloat16* sel_Al(int s) {
    if (s == 1) return g_Aal;
    if (s == 2) return g_Abl;
    if (s == 3) return g_Iml;
    return g_Bl + OFF_G0;
}
__device__ __forceinline__ const int* sel_list(int s, const int* ext) {
    if (s == 1) return g_list1;
    if (s == 2) return g_listR;
    if (s == 3) return ext;
    return nullptr;
}
__device__ __forceinline__ const int* sel_cnt(int s) {
    if (s == 1) return &g_cnt1;
    if (s == 2) return &g_cntR;
    return nullptr;
}
__device__ __forceinline__ int img_row(int r) {
    return (r / I_) * PER_ + W_ + (r % I_);
}

__device__ __forceinline__ void split_store(__nv_bfloat16* ph, __nv_bfloat16* pl, float v) {
    __nv_bfloat16 h = __float2bfloat16(v);
    __nv_bfloat16 l = __float2bfloat16(v - __bfloat162float(h));
    *ph = h; *pl = l;
}

// write a 300-dim feature into APa split (ld=384, zero-padded)
__device__ __forceinline__ void feat_out(int node, int tid, float v0, float v1, float v2) {
    size_t base = (size_t)node * 384;
    split_store(g_Aah + base + tid, g_Aal + base + tid, v0);
    split_store(g_Aah + base + tid + 128, g_Aal + base + tid + 128, v1);
    int d2 = tid + 256;
    if (d2 < 300) {
        split_store(g_Aah + base + d2, g_Aal + base + d2, v2);
    } else {
        g_Aah[base + d2] = __float2bfloat16(0.f);
        g_Aal[base + d2] = __float2bfloat16(0.f);
    }
}

// ---------------- staged feature kernels ----------------
__global__ void k_feat1(const int* __restrict__ aw,
                        const int* __restrict__ sent, const float* __restrict__ smask,
                        const float* __restrict__ we) {
    int node = blockIdx.x;
    int b = node / PER_, p = node - b * PER_;
    int tid = threadIdx.x;
    float v0 = 0.f, v1 = 0.f, v2 = 0.f;

    if (p < W_) {
        const float* row = we + (size_t)aw[(size_t)b * W_ + p] * 300;
        v0 = row[tid]; v1 = row[tid + 128];
        if (tid < 44) v2 = row[tid + 256];
    } else if (p >= W_ + I_ && p < W_ + I_ + S_) {
        int s = p - (W_ + I_);
        const int*   sw = sent + ((size_t)b * S_ + s) * T_;
        const float* mk = smask + ((size_t)b * S_ + s) * T_;
        float c = 0.f, a0 = 0.f, a1 = 0.f, a2 = 0.f;
#pragma unroll 4
        for (int t = 0; t < T_; t++) {
            float m = mk[t]; c += m;
            const float* row = we + (size_t)sw[t] * 300;
            a0 += m * row[tid];
            a1 += m * row[tid + 128];
            if (tid < 44) a2 += m * row[tid + 256];
        }
        float inv = 1.f / (c == 0.f ? 1.f : c);
        v0 = a0 * inv; v1 = a1 * inv; v2 = a2 * inv;
        float* sf = g_SF + ((size_t)b * S_ + s) * 300;
        sf[tid] = v0; sf[tid + 128] = v1;
        if (tid < 44) sf[tid + 256] = v2;
    } else if (p >= W_ + I_ + S_) {
        return;
    }
    feat_out(node, tid, v0, v1, v2);
}

__device__ __forceinline__ void utt_from_cache(const int* __restrict__ utts,
                                               const float* __restrict__ umask,
                                               int b, int u, int tid,
                                               float& o0, float& o1, float& o2) {
    float c = 0.f, a0 = 0.f, a1 = 0.f, a2 = 0.f;
#pragma unroll
    for (int t = 0; t < US_; t++) {
        size_t e = ((size_t)b * U_ + u) * US_ + t;
        float m = umask[e]; c += m;
        const float* sf = g_SF + ((size_t)b * S_ + utts[e]) * 300;
        a0 += m * sf[tid];
        a1 += m * sf[tid + 128];
        if (tid < 44) a2 += m * sf[tid + 256];
    }
    float inv = 1.f / (c == 0.f ? 1.f : c);
    o0 = a0 * inv; o1 = a1 * inv; o2 = a2 * inv;
}

__global__ void k_feat23(const int* __restrict__ utts, const float* __restrict__ umask) {
    int i = blockIdx.x;
    int b = i / (U_ + 1), q = i - b * (U_ + 1);
    int tid = threadIdx.x;
    if (q < U_) {
        float v0, v1, v2;
        utt_from_cache(utts, umask, b, q, tid, v0, v1, v2);
        feat_out(b * PER_ + W_ + I_ + S_ + q, tid, v0, v1, v2);
    } else {
        float a0 = 0.f, a1 = 0.f, a2 = 0.f;
        for (int u = 0; u < U_; u++) {
            float t0, t1, t2;
            utt_from_cache(utts, umask, b, u, tid, t0, t1, t2);
            a0 += t0; a1 += t1; a2 += t2;
        }
        const float inv = 1.f / (float)U_;
        feat_out(b * PER_ + W_ + I_ + S_ + U_, tid, a0 * inv, a1 * inv, a2 * inv);
    }
}

// ---------------- image feats split ----------------
__global__ void k_splitImg(const float* __restrict__ A) {
    long total = 256L * 2048 / 4;
    long stride = (long)gridDim.x * blockDim.x;
    for (long i = (long)blockIdx.x * blockDim.x + threadIdx.x; i < total; i += stride) {
        long e = i * 4;
        float4 v = *(const float4*)(A + e);
        __nv_bfloat16 h0 = __float2bfloat16(v.x), h1 = __float2bfloat16(v.y);
        __nv_bfloat16 h2 = __float2bfloat16(v.z), h3 = __float2bfloat16(v.w);
        g_Imh[e] = h0; g_Imh[e+1] = h1; g_Imh[e+2] = h2; g_Imh[e+3] = h3;
        g_Iml[e]   = __float2bfloat16(v.x - __bfloat162float(h0));
        g_Iml[e+1] = __float2bfloat16(v.y - __bfloat162float(h1));
        g_Iml[e+2] = __float2bfloat16(v.z - __bfloat162float(h2));
        g_Iml[e+3] = __float2bfloat16(v.w - __bfloat162float(h3));
    }
}

// ---------------- weight splits: 3 transposed + 2 plain ----------------
__global__ void k_splitWall(const float* __restrict__ g0, const float* __restrict__ g1,
                            const float* __restrict__ g2, const float* __restrict__ wt,
                            const float* __restrict__ wi) {
    int z = blockIdx.z;
    int tx = threadIdx.x, ty = threadIdx.y;
    if (z < 3) {
        const float* W; int N; size_t off;
        if (z == 0)      { W = g0; N = 1024; off = OFF_G0; }
        else if (z == 1) { W = g1; N = 1024; off = OFF_G1; }
        else             { W = g2; N = 512;  off = OFF_G2; }
        const int K = 1024, KP = 1024;
        int nt = blockIdx.x * 32, kt = blockIdx.y * 32;
        if (nt >= N || kt >= KP) return;
        __shared__ float tile[32][33];
#pragma unroll
        for (int i = 0; i < 4; i++) {
            int k = kt + ty + i * 8;
            tile[ty + i * 8][tx] = (k < K) ? W[(size_t)k * N + nt + tx] : 0.f;
        }
        __syncthreads();
#pragma unroll
        for (int i = 0; i < 4; i++) {
            int n = nt + ty + i * 8;
            int k = kt + tx;
            float v = tile[tx][ty + i * 8];
            __nv_bfloat16 h = __float2bfloat16(v);
            g_Bh[off + (size_t)n * KP + k] = h;
            g_Bl[off + (size_t)n * KP + k] = __float2bfloat16(v - __bfloat162float(h));
        }
    } else {
        const float* W; int rows, padRows; size_t off;
        if (z == 3) { W = wt; rows = 300;  padRows = 384;  off = OFF_TXTP; }
        else        { W = wi; rows = 2048; padRows = 2048; off = OFF_IMGP; }
        const int cols = 1024;
        int r0 = blockIdx.y * 32, c0 = blockIdx.x * 32;
        if (r0 >= padRows || c0 >= cols) return;
#pragma unroll
        for (int i = 0; i < 4; i++) {
            int r = r0 + ty + i * 8, c = c0 + tx;
            float v = (r < rows) ? W[(size_t)r * cols + c] : 0.f;
            __nv_bfloat16 h = __float2bfloat16(v);
            g_Bh[off + (size_t)r * cols + c] = h;
            g_Bl[off + (size_t)r * cols + c] = __float2bfloat16(v - __bfloat162float(h));
        }
    }
}

// fold fc biases through G0: g_bT = b_txt@G0, g_bI = b_img@G0 (warp per column)
__global__ void k_bias(const float* __restrict__ tb, const float* __restrict__ ib,
                       const float* __restrict__ g0) {
    int gw = (blockIdx.x * blockDim.x + threadIdx.x) >> 5;   // 0..2047
    int lane = threadIdx.x & 31;
    if (gw >= 2048) return;
    int col = gw & 1023;
    const float* bv = (gw < 1024) ? tb : ib;
    float s = 0.f;
#pragma unroll 4
    for (int j = lane; j < 1024; j += 32)
        s += bv[j] * g0[(size_t)j * 1024 + col];
#pragma unroll
    for (int o = 16; o; o >>= 1) s += __shfl_xor_sync(0xffffffffu, s, o);
    if (lane == 0) { if (gw < 1024) g_bT[col] = s; else g_bI[col] = s; }
}

// ---------------- pipelined mma.sync bf16x3 GEMM ----------------
// gridDim.z > 1 enables split-K: each z handles nChunks chunks starting at
// blockIdx.z * nChunks; cMode 1 then uses atomicAdd into pre-zeroed F rows.
#define SROW 40
#define TILEB (128 * SROW * 2)
#define STAGEB (4 * TILEB)
#define SMEM_GEMM (2 * STAGEB)

__global__ __launch_bounds__(256, 2)
void mma_gemm(int nChunks, int KP, size_t bOff,
              int aSel, int cMode, int ldC, size_t cOff,
              int cntSel, int cntImm, int aListSel, int outListSel,
              int biasSel, const float* __restrict__ al, const float* __restrict__ ar,
              int NH, int skipImg) {
    const int* cp = sel_cnt(cntSel);
    int cnt = cp ? *cp : cntImm;
    int row0 = blockIdx.y * 128;
    if (row0 >= cnt) return;
    int col0 = blockIdx.x * 128;
    int chunkBase = blockIdx.z * nChunks;
    bool splitK = gridDim.z > 1;

    extern __shared__ char sm[];
    uint32_t sb = smem_u32(sm);

    const __nv_bfloat16* Ah = sel_Ah(aSel);
    const __nv_bfloat16* Al = sel_Al(aSel);
    const __nv_bfloat16* Bh = g_Bh + bOff;
    const __nv_bfloat16* Bl = g_Bl + bOff;
    const int* alist = sel_list(aListSel, nullptr);

    int tid = threadIdx.x, lane = tid & 31, wid = tid >> 5;
    int wm = wid & 1, wn = wid >> 1;

    float acc[4][4][4];
#pragma unroll
    for (int i = 0; i < 4; i++)
#pragma unroll
        for (int j = 0; j < 4; j++)
#pragma unroll
            for (int q = 0; q < 4; q++) acc[i][j][q] = 0.f;

    int lrow = tid >> 2;
    int lk   = (tid & 3) * 8;

    int arow0g = 0, arow1g = 0; int av0 = 0, av1 = 0;
    {
        int r0 = row0 + lrow, r1 = row0 + lrow + 64;
        if (r0 < cnt) {
            av0 = 16;
            arow0g = (aListSel == 5) ? img_row(r0) : (alist ? alist[r0] : r0);
        }
        if (r1 < cnt) {
            av1 = 16;
            arow1g = (aListSel == 5) ? img_row(r1) : (alist ? alist[r1] : r1);
        }
    }
    int brow0 = col0 + lrow, brow1 = col0 + lrow + 64;

#define LOAD_CHUNK(c, s) do {                                                   \
        int k0g = (chunkBase + (c)) * 32;                                       \
        uint32_t st = sb + (s) * STAGEB;                                        \
        uint32_t d0 = st + (uint32_t)(lrow * SROW + lk) * 2;                    \
        uint32_t d1 = st + (uint32_t)((lrow + 64) * SROW + lk) * 2;             \
        cpa16(d0,             Ah + (size_t)arow0g * KP + k0g + lk, av0);        \
        cpa16(d1,             Ah + (size_t)arow1g * KP + k0g + lk, av1);        \
        cpa16(d0 + TILEB,     Al + (size_t)arow0g * KP + k0g + lk, av0);        \
        cpa16(d1 + TILEB,     Al + (size_t)arow1g * KP + k0g + lk, av1);        \
        cpa16(d0 + 2 * TILEB, Bh + (size_t)brow0 * KP + k0g + lk, 16);          \
        cpa16(d1 + 2 * TILEB, Bh + (size_t)brow1 * KP + k0g + lk, 16);          \
        cpa16(d0 + 3 * TILEB, Bl + (size_t)brow0 * KP + k0g + lk, 16);          \
        cpa16(d1 + 3 * TILEB, Bl + (size_t)brow1 * KP + k0g + lk, 16);          \
        cpa_commit();                                                           \
    } while (0)

    int aR = (lane & 15), aC = (lane >> 4) << 3;
    int bR = (lane & 7),  bC = ((lane >> 3) & 1) << 3;

    LOAD_CHUNK(0, 0);
    for (int c = 0; c < nChunks; c++) {
        if (c + 1 < nChunks) {
            LOAD_CHUNK(c + 1, (c + 1) & 1);
            cpa_wait<1>();
        } else {
            cpa_wait<0>();
        }
        __syncthreads();
        uint32_t st = sb + (uint32_t)(c & 1) * STAGEB;
#pragma unroll
        for (int ks = 0; ks < 2; ks++) {
            int k0 = ks * 16;
            uint32_t a[4][4], bh[4][2], bl[4][2];
            uint32_t aoff[4];
#pragma unroll
            for (int am = 0; am < 4; am++) {
                aoff[am] = st + (uint32_t)((wm * 64 + am * 16 + aR) * SROW + k0 + aC) * 2;
                ldsm_x4(a[am], aoff[am]);
            }
#pragma unroll
            for (int bn = 0; bn < 4; bn++) {
                uint32_t off = st + (uint32_t)((wn * 32 + bn * 8 + bR) * SROW + k0 + bC) * 2;
                ldsm_x2(bh[bn], off + 2 * TILEB);
                ldsm_x2(bl[bn], off + 3 * TILEB);
            }
#pragma unroll
            for (int am = 0; am < 4; am++)
#pragma unroll
                for (int bn = 0; bn < 4; bn++)
                    mma16816(acc[am][bn], a[am], bh[bn]);
#pragma unroll
            for (int am = 0; am < 4; am++)
#pragma unroll
                for (int bn = 0; bn < 4; bn++)
                    mma16816(acc[am][bn], a[am], bl[bn]);
#pragma unroll
            for (int am = 0; am < 4; am++)
                ldsm_x4(a[am], aoff[am] + TILEB);
#pragma unroll
            for (int am = 0; am < 4; am++)
#pragma unroll
                for (int bn = 0; bn < 4; bn++)
                    mma16816(acc[am][bn], a[am], bh[bn]);
        }
        __syncthreads();
    }
#undef LOAD_CHUNK

    // ---------------- epilogue ----------------
    const int* ol = sel_list(outListSel, nullptr);
    const float* bias = (biasSel == 1) ? g_bT : ((biasSel == 2) ? g_bI : nullptr);
    int h = 0;
    if (al) h = (col0 + wn * 32) / (ldC / NH);

#pragma unroll
    for (int am = 0; am < 4; am++) {
#pragma unroll
        for (int part = 0; part < 2; part++) {
            int r = row0 + wm * 64 + am * 16 + (lane >> 2) + part * 8;
            bool valid = r < cnt;
            int orow = 0;
            if (valid) {
                if (outListSel == 5)      orow = img_row(r);
                else if (ol)              orow = ol[r];
                else                      orow = r;
            }
            bool doE = valid && (al != nullptr);
            if (doE && skipImg) {
                int p = orow % PER_;
                if (p >= W_ && p < W_ + I_) doE = false;
            }
            float sl = 0.f, sr = 0.f;
#pragma unroll
            for (int bn = 0; bn < 4; bn++) {
                int cidx = col0 + wn * 32 + bn * 8 + (lane & 3) * 2;
                float x = acc[am][bn][part * 2 + 0];
                float y = acc[am][bn][part * 2 + 1];
                if (bias) { x += bias[cidx]; y += bias[cidx + 1]; }
                if (doE) {
                    sl += x * al[cidx] + y * al[cidx + 1];
                    sr += x * ar[cidx] + y * ar[cidx + 1];
                }
                if (valid) {
                    if (cMode == 1) {
                        float* dst = &g_F[(size_t)orow * ldC + cidx];
                        if (splitK) {
                            atomicAdd(dst, x);
                            atomicAdd(dst + 1, y);
                        } else {
                            float2 v; v.x = x; v.y = y;
                            *(float2*)dst = v;
                        }
                    } else if (cMode == 2) {
                        size_t o = (size_t)orow * 1024 + cidx;
                        __nv_bfloat16 hx = __float2bfloat16(x);
                        __nv_bfloat16 hy = __float2bfloat16(y);
                        __nv_bfloat162 H; H.x = hx; H.y = hy;
                        __nv_bfloat162 L;
                        L.x = __float2bfloat16(x - __bfloat162float(hx));
                        L.y = __float2bfloat16(y - __bfloat162float(hy));
                        *(__nv_bfloat162*)&g_Abh[o] = H;
                        *(__nv_bfloat162*)&g_Abl[o] = L;
                    } else {
                        size_t o = cOff + (size_t)orow * ldC + cidx;
                        __nv_bfloat16 hx = __float2bfloat16(x);
                        __nv_bfloat16 hy = __float2bfloat16(y);
                        __nv_bfloat162 H; H.x = hx; H.y = hy;
                        __nv_bfloat162 L;
                        L.x = __float2bfloat16(x - __bfloat162float(hx));
                        L.y = __float2bfloat16(y - __bfloat162float(hy));
                        *(__nv_bfloat162*)&g_Bh[o] = H;
                        *(__nv_bfloat162*)&g_Bl[o] = L;
                    }
                }
            }
            if (al) {
                sl += __shfl_xor_sync(0xffffffffu, sl, 1);
                sl += __shfl_xor_sync(0xffffffffu, sl, 2);
                sr += __shfl_xor_sync(0xffffffffu, sr, 1);
                sr += __shfl_xor_sync(0xffffffffu, sr, 2);
                if (doE && (lane & 3) == 0) {
                    atomicAdd(&g_EL[orow * NH + h], sl);
                    atomicAdd(&g_ER[orow * NH + h], sr);
                }
            }
        }
    }
}

// ---------------- sets/CSR ----------------
__global__ void k_init() {
    int i = blockIdx.x * blockDim.x + threadIdx.x;
    if (i < NND) {
        g_A1f[i] = 0; g_R1f[i] = 0;
        g_deg[i] = 0;
#pragma unroll
        for (int h = 0; h < 4; h++) { g_EL[i * 4 + h] = 0.f; g_ER[i * 4 + h] = 0.f; }
    }
    if (i == NND) g_deg[NND] = 0;
    if (i == 0) { g_cnt1 = 0; g_cntR = 0; }
}
__global__ void k_markA1(const int* __restrict__ src, const int* __restrict__ dst,
                         const int* __restrict__ sid, int E) {
    int e = blockIdx.x * blockDim.x + threadIdx.x;
    if (e < E) {
        int d = dst[e];
        if (d == sid[0] || d == sid[1] || d == sid[2] || d == sid[3])
            g_A1f[src[e]] = 1;
    }
}
__global__ void k_markR1(const int* __restrict__ src, const int* __restrict__ dst, int E) {
    int e = blockIdx.x * blockDim.x + threadIdx.x;
    if (e < E && g_A1f[dst[e]]) g_R1f[src[e]] = 1;
}
__global__ void k_compact_count(const int* __restrict__ dst, int E) {
    int i = blockIdx.x * blockDim.x + threadIdx.x;
    if (i < NND) {
        if (g_A1f[i]) g_list1[atomicAdd(&g_cnt1, 1)] = i;
        if (g_R1f[i]) g_listR[atomicAdd(&g_cntR, 1)] = i;
    }
    if (i < E) atomicAdd(&g_deg[dst[i]], 1);
}
__global__ void k_scan() {
    __shared__ int sh[1024];
    int tid = threadIdx.x;
    const int chunk = (NND + 1023) >> 10;
    int lo = tid * chunk;
    int hi = lo + chunk; if (hi > NND) hi = NND; if (lo > NND) lo = NND;
    int sum = 0;
    for (int i = lo; i < hi; i++) sum += g_deg[i];
    sh[tid] = sum; __syncthreads();
    for (int d = 1; d < 1024; d <<= 1) {
        int v = 0;
        if (tid >= d) v = sh[tid - d];
        __syncthreads();
        if (tid >= d) sh[tid] += v;
        __syncthreads();
    }
    int run = (tid == 0) ? 0 : sh[tid - 1];
    for (int i = lo; i < hi; i++) {
        g_off[i] = run; g_cur[i] = run; run += g_deg[i];
    }
    if (tid == 1023) g_off[NND] = run;
}
__global__ void k_fill(const int* __restrict__ src, const int* __restrict__ dst, int E) {
    int e = blockIdx.x * blockDim.x + threadIdx.x;
    if (e < E) {
        int p = atomicAdd(&g_cur[dst[e]], 1);
        g_esrc[p] = src[e];
    }
}

// zero EL/ER (stride NH) and F rows (width ldF) for a compacted list
__global__ void k_zeroELR(int which, int NH, int ldF) {
    int n = (which == 1) ? g_cnt1 : g_cntR;
    const int* list = (which == 1) ? g_list1 : g_listR;
    long total = (long)n * ldF;
    long stride = (long)gridDim.x * blockDim.x;
    for (long i = (long)blockIdx.x * blockDim.x + threadIdx.x; i < total; i += stride) {
        int idx = (int)(i / ldF);
        int c = (int)(i - (long)idx * ldF);
        int nd = list[idx];
        g_F[(size_t)nd * ldF + c] = 0.f;
        if (c < NH) { g_EL[nd * NH + c] = 0.f; g_ER[nd * NH + c] = 0.f; }
    }
}

// ---------------- GAT attention ----------------
template <int NH, int DD, bool ACT>
__global__ void k_attn(const float* __restrict__ bias, int outMode,
                       int listSel, int cntSel, int cntImm,
                       const int* __restrict__ extList, float* __restrict__ extOut) {
    constexpr int WID = NH * DD;
    constexpr int NE  = WID / 128;
    constexpr int CE  = 128 / NH;
    const int* cp = sel_cnt(cntSel);
    int cnt = cp ? *cp : cntImm;
    const int* list = sel_list(listSel, extList);
    int tid = threadIdx.x;

    __shared__ float s_er[NH], s_m[NH], s_iz[NH];
    __shared__ float red[128];
    __shared__ float swt[32 * NH];
    __shared__ int   ssrc[32];

    for (int bi = blockIdx.x; bi < cnt; bi += gridDim.x) {
        int nd = list ? list[bi] : bi;
        int lo  = g_off[nd];
        int deg = g_off[nd + 1] - lo;

        if (tid < NH) s_er[tid] = g_ER[nd * NH + tid];
        __syncthreads();

        int h  = tid / CE;
        int e0 = tid % CE;
        float erh = s_er[h];

        float lmax = -1e30f;
        for (int e = e0; e < deg; e += CE) {
            int s = g_esrc[lo + e];
            float x = g_EL[s * NH + h] + erh;
            x = x > 0.f ? x : 0.2f * x;
            lmax = fmaxf(lmax, x);
        }
        red[tid] = lmax; __syncthreads();
#pragma unroll
        for (int st = CE / 2; st > 0; st >>= 1) {
            if (e0 < st) red[tid] = fmaxf(red[tid], red[tid + st]);
            __syncthreads();
        }
        if (e0 == 0) s_m[h] = red[tid];
        __syncthreads();
        float mh = s_m[h];

        float lsum = 0.f;
        for (int e = e0; e < deg; e += CE) {
            int s = g_esrc[lo + e];
            float x = g_EL[s * NH + h] + erh;
            x = x > 0.f ? x : 0.2f * x;
            lsum += expf(x - mh);
        }
        red[tid] = lsum; __syncthreads();
#pragma unroll
        for (int st = CE / 2; st > 0; st >>= 1) {
            if (e0 < st) red[tid] += red[tid + st];
            __syncthreads();
        }
        if (e0 == 0) s_iz[h] = 1.f / red[tid];
        __syncthreads();

        float accv[NE];
        int hd[NE];
#pragma unroll
        for (int j = 0; j < NE; j++) { accv[j] = 0.f; hd[j] = (tid + j * 128) / DD; }

        for (int base = 0; base < deg; base += 32) {
            int mcnt = deg - base; if (mcnt > 32) mcnt = 32;
            if (tid < 32 * NH) {
                int eL = tid / NH, hh = tid - (tid / NH) * NH;
                float wv = 0.f;
                if (eL < mcnt) {
                    int s = g_esrc[lo + base + eL];
                    float x = g_EL[s * NH + hh] + s_er[hh];
                    x = x > 0.f ? x : 0.2f * x;
                    wv = expf(x - s_m[hh]) * s_iz[hh];
                    if (hh == 0) ssrc[eL] = s;
                }
                swt[eL * NH + hh] = wv;
            }
            __syncthreads();
            for (int eL = 0; eL < mcnt; eL++) {
                int s = ssrc[eL];
                const float* fr = g_F + (size_t)s * WID;
#pragma unroll
                for (int j = 0; j < NE; j++)
                    accv[j] += swt[eL * NH + hd[j]] * fr[tid + j * 128];
            }
            __syncthreads();
        }

#pragma unroll
        for (int j = 0; j < NE; j++) {
            int c = tid + j * 128;
            float v = accv[j] + bias[c];
            if (ACT) v = v > 0.f ? v : (expf(v) - 1.f);
            if (outMode == 3) {
                extOut[(size_t)bi * WID + c] = v;
            } else {
                __nv_bfloat16* dh = (outMode == 1 ? g_Aah : g_Abh);
                __nv_bfloat16* dl = (outMode == 1 ? g_Aal : g_Abl);
                split_store(dh + (size_t)nd * 1024 + c, dl + (size_t)nd * 1024 + c, v);
            }
        }
    }
}

// ---------------- launch ----------------
extern "C" void kernel_launch(void* const* d_in, const int* in_sizes, int n_in,
                              void* d_out, int out_size) {
    const int*   all_words      = (const int*)  d_in[0];
    const float* image_feats    = (const float*)d_in[1];
    const int*   sentences      = (const int*)  d_in[2];
    const float* sentence_mask  = (const float*)d_in[3];
    const int*   utterances     = (const int*)  d_in[4];
    const float* utterance_mask = (const float*)d_in[5];
    const int*   session_ids    = (const int*)  d_in[6];
    const int*   edge_src       = (const int*)  d_in[7];
    const int*   edge_dst       = (const int*)  d_in[8];
    const float* word_embed     = (const float*)d_in[9];
    const float* text_fc_w      = (const float*)d_in[10];
    const float* text_fc_b      = (const float*)d_in[11];
    const float* image_fc_w     = (const float*)d_in[12];
    const float* image_fc_b     = (const float*)d_in[13];
    const float* gat0_fc = (const float*)d_in[14];
    const float* gat0_al = (const float*)d_in[15];
    const float* gat0_ar = (const float*)d_in[16];
    const float* gat0_b  = (const float*)d_in[17];
    const float* gat1_fc = (const float*)d_in[18];
    const float* gat1_al = (const float*)d_in[19];
    const float* gat1_ar = (const float*)d_in[20];
    const float* gat1_b  = (const float*)d_in[21];
    const float* gat2_fc = (const float*)d_in[22];
    const float* gat2_al = (const float*)d_in[23];
    const float* gat2_ar = (const float*)d_in[24];
    const float* gat2_b  = (const float*)d_in[25];
    float* out = (float*)d_out;
    int E = in_sizes[7];

    cudaFuncSetAttribute(mma_gemm, cudaFuncAttributeMaxDynamicSharedMemorySize, SMEM_GEMM);

    // features + weight prep
    k_feat1<<<NND, 128>>>(all_words, sentences, sentence_mask, word_embed);
    k_feat23<<<BB * (U_ + 1), 128>>>(utterances, utterance_mask);
    k_splitWall<<<dim3(32, 64, 5), dim3(32, 8)>>>(gat0_fc, gat1_fc, gat2_fc,
                                                  text_fc_w, image_fc_w);
    k_bias<<<256, 256>>>(text_fc_b, image_fc_b, gat0_fc);
    k_splitImg<<<512, 256>>>(image_feats);

    // sets + CSR (also zeroes EL/ER for layer 0)
    k_init<<<(NND + 256) / 256, 256>>>();
    k_markA1<<<(E + 255) / 256, 256>>>(edge_src, edge_dst, session_ids, E);
    k_markR1<<<(E + 255) / 256, 256>>>(edge_src, edge_dst, E);
    k_compact_count<<<(E + 255) / 256, 256>>>(edge_dst, E);
    k_scan<<<1, 1024>>>();
    k_fill<<<(E + 255) / 256, 256>>>(edge_src, edge_dst, E);

    // precompute fused weights: (W_txt@G0) and (W_img@G0), stored [N=1024, K]
    mma_gemm<<<dim3(3, 8), 256, SMEM_GEMM>>>(32, 1024, OFF_TXTP, 4, 4, 384, OFF_TXTF,
                                             0, 1024, 0, 0, 0, nullptr, nullptr, 1, 0);
    mma_gemm<<<dim3(16, 8), 256, SMEM_GEMM>>>(32, 1024, OFF_IMGP, 4, 4, 2048, OFF_IMGF,
                                              0, 1024, 0, 0, 0, nullptr, nullptr, 1, 0);

    // layer-0 f (fused): text rows -> F (+elr, skip image rows), then image rows
    mma_gemm<<<dim3(8, 68), 256, SMEM_GEMM>>>(12, 384, OFF_TXTF, 1, 1, 1024, 0,
                                              0, NND, 0, 0, 1, gat0_al, gat0_ar, 4, 1);
    mma_gemm<<<dim3(8, 2), 256, SMEM_GEMM>>>(64, 2048, OFF_IMGF, 3, 1, 1024, 0,
                                             0, 256, 0, 5, 2, gat0_al, gat0_ar, 4, 0);
    k_attn<4, 256, true><<<2176, 128>>>(gat0_b, 1, 2, 2, 0, nullptr, nullptr);

    // layer 1: zero EL/ER + F rows(listR), then split-K=2 GEMM (atomicAdd into F)
    k_zeroELR<<<256, 256>>>(2, 4, 1024);
    mma_gemm<<<dim3(8, 68, 2), 256, SMEM_GEMM>>>(16, 1024, OFF_G1, 1, 1, 1024, 0,
                                                 2, 0, 2, 2, 0, gat1_al, gat1_ar, 4, 0);
    k_attn<4, 256, true><<<2176, 128>>>(gat1_b, 2, 1, 1, 0, nullptr, nullptr);

    // layer 2: zero EL/ER + F rows(list1), then split-K=4 GEMM
    k_zeroELR<<<64, 256>>>(1, 1, 512);
    mma_gemm<<<dim3(4, 68, 4), 256, SMEM_GEMM>>>(8, 1024, OFF_G2, 2, 1, 512, 0,
                                                 1, 0, 1, 1, 0, gat2_al, gat2_ar, 1, 0);
    k_attn<1, 512, false><<<32, 128>>>(gat2_b, 3, 3, 0, BB, session_ids, out);
}

// round 17
// speedup vs baseline: 1.1328x; 1.1126x over previous
#include <cuda_runtime.h>
#include <cuda_bf16.h>
#include <math.h>
#include <stdint.h>

// Problem constants
#define BB   4
#define W_   2000
#define I_   64
#define S_   64
#define T_   24
#define U_   32
#define US_  2
#define PER_ 2161
#define NND  8644
#define EMAX 147456

// weight regions in g_Bh/g_Bl (bf16 element offsets)
#define OFF_G0   0            // G0^T [1024,1024]
#define OFF_G1   1048576      // G1^T [1024,1024]
#define OFF_G2   2097152      // G2^T [512,1024]
#define OFF_TXTP 2621440      // W_txt plain [384(pad300),1024]
#define OFF_IMGP 3014656      // W_img plain [2048,1024]
#define OFF_TXTF 5111808      // fused (W_txt@G0) [1024,384]
#define OFF_IMGF 5505024      // fused (W_img@G0) [1024,2048]
#define BTOT     7602176

// ---------------- scratch (device globals; no allocation) ----------------
__device__ float g_F[(size_t)NND * 1024];
__device__ __nv_bfloat16 g_Aah[(size_t)NND * 1024];  // APa hi
__device__ __nv_bfloat16 g_Aal[(size_t)NND * 1024];  // APa lo
__device__ __nv_bfloat16 g_Abh[(size_t)NND * 1024];  // APb hi
__device__ __nv_bfloat16 g_Abl[(size_t)NND * 1024];  // APb lo
__device__ __nv_bfloat16 g_Imh[256 * 2048];
__device__ __nv_bfloat16 g_Iml[256 * 2048];
__device__ __nv_bfloat16 g_Bh[BTOT];
__device__ __nv_bfloat16 g_Bl[BTOT];
__device__ float g_bT[1024];            // b_txt @ G0
__device__ float g_bI[1024];            // b_img @ G0
__device__ float g_SF[BB * S_ * 300];
__device__ float g_EL[NND * 4];
__device__ float g_ER[NND * 4];
__device__ int   g_deg[NND + 1];
__device__ int   g_off[NND + 1];
__device__ int   g_cur[NND];
__device__ int   g_esrc[EMAX];
__device__ unsigned char g_A1f[NND], g_R1f[NND];
__device__ int   g_list1[NND], g_listR[NND];
__device__ int   g_cnt1, g_cntR;

__device__ __forceinline__ uint32_t smem_u32(const void* p) {
    uint32_t a;
    asm("{ .reg .u64 t; cvta.to.shared.u64 t, %1; cvt.u32.u64 %0, t; }" : "=r"(a) : "l"(p));
    return a;
}

// ---------------- mma.sync / cp.async helpers ----------------
__device__ __forceinline__ void ldsm_x4(uint32_t* r, uint32_t addr) {
    asm volatile("ldmatrix.sync.aligned.m8n8.x4.shared.b16 {%0,%1,%2,%3}, [%4];"
                 : "=r"(r[0]), "=r"(r[1]), "=r"(r[2]), "=r"(r[3]) : "r"(addr));
}
__device__ __forceinline__ void ldsm_x2(uint32_t* r, uint32_t addr) {
    asm volatile("ldmatrix.sync.aligned.m8n8.x2.shared.b16 {%0,%1}, [%2];"
                 : "=r"(r[0]), "=r"(r[1]) : "r"(addr));
}
__device__ __forceinline__ void mma16816(float* c, const uint32_t* a, const uint32_t* b) {
    asm volatile(
        "mma.sync.aligned.m16n8k16.row.col.f32.bf16.bf16.f32 "
        "{%0,%1,%2,%3},{%4,%5,%6,%7},{%8,%9},{%0,%1,%2,%3};"
        : "+f"(c[0]), "+f"(c[1]), "+f"(c[2]), "+f"(c[3])
        : "r"(a[0]), "r"(a[1]), "r"(a[2]), "r"(a[3]), "r"(b[0]), "r"(b[1]));
}
__device__ __forceinline__ void cpa16(uint32_t dst, const void* src, int sz) {
    asm volatile("cp.async.cg.shared.global [%0], [%1], 16, %2;"
                 :: "r"(dst), "l"(src), "r"(sz));
}
__device__ __forceinline__ void cpa_commit() {
    asm volatile("cp.async.commit_group;");
}
template <int N>
__device__ __forceinline__ void cpa_wait() {
    asm volatile("cp.async.wait_group %0;" :: "n"(N));
}

// ---------------- selectors ----------------
__device__ __forceinline__ const __nv_bfloat16* sel_Ah(int s) {
    if (s == 1) return g_Aah;
    if (s == 2) return g_Abh;
    if (s == 3) return g_Imh;
    return g_Bh + OFF_G0;                 // 4: G0^T as A operand
}
__device__ __forceinline__ const __nv_bfloat16* sel_Al(int s) {
    if (s == 1) return g_Aal;
    if (s == 2) return g_Abl;
    if (s == 3) return g_Iml;
    return g_Bl + OFF_G0;
}
__device__ __forceinline__ const int* sel_list(int s) {
    if (s == 1) return g_list1;
    if (s == 2) return g_listR;
    return nullptr;
}
__device__ __forceinline__ const int* sel_cnt(int s) {
    if (s == 1) return &g_cnt1;
    if (s == 2) return &g_cntR;
    return nullptr;
}
__device__ __forceinline__ int img_row(int r) {
    return (r / I_) * PER_ + W_ + (r % I_);
}

__device__ __forceinline__ void split_store(__nv_bfloat16* ph, __nv_bfloat16* pl, float v) {
    __nv_bfloat16 h = __float2bfloat16(v);
    __nv_bfloat16 l = __float2bfloat16(v - __bfloat162float(h));
    *ph = h; *pl = l;
}

// write a 300-dim feature into APa split (ld=384, zero-padded)
__device__ __forceinline__ void feat_out(int node, int tid, float v0, float v1, float v2) {
    size_t base = (size_t)node * 384;
    split_store(g_Aah + base + tid, g_Aal + base + tid, v0);
    split_store(g_Aah + base + tid + 128, g_Aal + base + tid + 128, v1);
    int d2 = tid + 256;
    if (d2 < 300) {
        split_store(g_Aah + base + d2, g_Aal + base + d2, v2);
    } else {
        g_Aah[base + d2] = __float2bfloat16(0.f);
        g_Aal[base + d2] = __float2bfloat16(0.f);
    }
}

// ---------------- staged feature kernels ----------------
__global__ void k_feat1(const int* __restrict__ aw,
                        const int* __restrict__ sent, const float* __restrict__ smask,
                        const float* __restrict__ we) {
    int node = blockIdx.x;
    int b = node / PER_, p = node - b * PER_;
    int tid = threadIdx.x;
    float v0 = 0.f, v1 = 0.f, v2 = 0.f;

    if (p < W_) {
        const float* row = we + (size_t)aw[(size_t)b * W_ + p] * 300;
        v0 = row[tid]; v1 = row[tid + 128];
        if (tid < 44) v2 = row[tid + 256];
    } else if (p >= W_ + I_ && p < W_ + I_ + S_) {
        int s = p - (W_ + I_);
        const int*   sw = sent + ((size_t)b * S_ + s) * T_;
        const float* mk = smask + ((size_t)b * S_ + s) * T_;
        float c = 0.f, a0 = 0.f, a1 = 0.f, a2 = 0.f;
#pragma unroll 4
        for (int t = 0; t < T_; t++) {
            float m = mk[t]; c += m;
            const float* row = we + (size_t)sw[t] * 300;
            a0 += m * row[tid];
            a1 += m * row[tid + 128];
            if (tid < 44) a2 += m * row[tid + 256];
        }
        float inv = 1.f / (c == 0.f ? 1.f : c);
        v0 = a0 * inv; v1 = a1 * inv; v2 = a2 * inv;
        float* sf = g_SF + ((size_t)b * S_ + s) * 300;
        sf[tid] = v0; sf[tid + 128] = v1;
        if (tid < 44) sf[tid + 256] = v2;
    } else if (p >= W_ + I_ + S_) {
        return;
    }
    feat_out(node, tid, v0, v1, v2);
}

__device__ __forceinline__ void utt_from_cache(const int* __restrict__ utts,
                                               const float* __restrict__ umask,
                                               int b, int u, int tid,
                                               float& o0, float& o1, float& o2) {
    float c = 0.f, a0 = 0.f, a1 = 0.f, a2 = 0.f;
#pragma unroll
    for (int t = 0; t < US_; t++) {
        size_t e = ((size_t)b * U_ + u) * US_ + t;
        float m = umask[e]; c += m;
        const float* sf = g_SF + ((size_t)b * S_ + utts[e]) * 300;
        a0 += m * sf[tid];
        a1 += m * sf[tid + 128];
        if (tid < 44) a2 += m * sf[tid + 256];
    }
    float inv = 1.f / (c == 0.f ? 1.f : c);
    o0 = a0 * inv; o1 = a1 * inv; o2 = a2 * inv;
}

__global__ void k_feat23(const int* __restrict__ utts, const float* __restrict__ umask) {
    int i = blockIdx.x;
    int b = i / (U_ + 1), q = i - b * (U_ + 1);
    int tid = threadIdx.x;
    if (q < U_) {
        float v0, v1, v2;
        utt_from_cache(utts, umask, b, q, tid, v0, v1, v2);
        feat_out(b * PER_ + W_ + I_ + S_ + q, tid, v0, v1, v2);
    } else {
        float a0 = 0.f, a1 = 0.f, a2 = 0.f;
        for (int u = 0; u < U_; u++) {
            float t0, t1, t2;
            utt_from_cache(utts, umask, b, u, tid, t0, t1, t2);
            a0 += t0; a1 += t1; a2 += t2;
        }
        const float inv = 1.f / (float)U_;
        feat_out(b * PER_ + W_ + I_ + S_ + U_, tid, a0 * inv, a1 * inv, a2 * inv);
    }
}

// ---------------- image feats split ----------------
__global__ void k_splitImg(const float* __restrict__ A) {
    long total = 256L * 2048 / 4;
    long stride = (long)gridDim.x * blockDim.x;
    for (long i = (long)blockIdx.x * blockDim.x + threadIdx.x; i < total; i += stride) {
        long e = i * 4;
        float4 v = *(const float4*)(A + e);
        __nv_bfloat16 h0 = __float2bfloat16(v.x), h1 = __float2bfloat16(v.y);
        __nv_bfloat16 h2 = __float2bfloat16(v.z), h3 = __float2bfloat16(v.w);
        g_Imh[e] = h0; g_Imh[e+1] = h1; g_Imh[e+2] = h2; g_Imh[e+3] = h3;
        g_Iml[e]   = __float2bfloat16(v.x - __bfloat162float(h0));
        g_Iml[e+1] = __float2bfloat16(v.y - __bfloat162float(h1));
        g_Iml[e+2] = __float2bfloat16(v.z - __bfloat162float(h2));
        g_Iml[e+3] = __float2bfloat16(v.w - __bfloat162float(h3));
    }
}

// ---------------- weight splits: 3 transposed + 2 plain ----------------
__global__ void k_splitWall(const float* __restrict__ g0, const float* __restrict__ g1,
                            const float* __restrict__ g2, const float* __restrict__ wt,
                            const float* __restrict__ wi) {
    int z = blockIdx.z;
    int tx = threadIdx.x, ty = threadIdx.y;
    if (z < 3) {
        const float* W; int N; size_t off;
        if (z == 0)      { W = g0; N = 1024; off = OFF_G0; }
        else if (z == 1) { W = g1; N = 1024; off = OFF_G1; }
        else             { W = g2; N = 512;  off = OFF_G2; }
        const int K = 1024, KP = 1024;
        int nt = blockIdx.x * 32, kt = blockIdx.y * 32;
        if (nt >= N || kt >= KP) return;
        __shared__ float tile[32][33];
#pragma unroll
        for (int i = 0; i < 4; i++) {
            int k = kt + ty + i * 8;
            tile[ty + i * 8][tx] = (k < K) ? W[(size_t)k * N + nt + tx] : 0.f;
        }
        __syncthreads();
#pragma unroll
        for (int i = 0; i < 4; i++) {
            int n = nt + ty + i * 8;
            int k = kt + tx;
            float v = tile[tx][ty + i * 8];
            __nv_bfloat16 h = __float2bfloat16(v);
            g_Bh[off + (size_t)n * KP + k] = h;
            g_Bl[off + (size_t)n * KP + k] = __float2bfloat16(v - __bfloat162float(h));
        }
    } else {
        const float* W; int rows, padRows; size_t off;
        if (z == 3) { W = wt; rows = 300;  padRows = 384;  off = OFF_TXTP; }
        else        { W = wi; rows = 2048; padRows = 2048; off = OFF_IMGP; }
        const int cols = 1024;
        int r0 = blockIdx.y * 32, c0 = blockIdx.x * 32;
        if (r0 >= padRows || c0 >= cols) return;
#pragma unroll
        for (int i = 0; i < 4; i++) {
            int r = r0 + ty + i * 8, c = c0 + tx;
            float v = (r < rows) ? W[(size_t)r * cols + c] : 0.f;
            __nv_bfloat16 h = __float2bfloat16(v);
            g_Bh[off + (size_t)r * cols + c] = h;
            g_Bl[off + (size_t)r * cols + c] = __float2bfloat16(v - __bfloat162float(h));
        }
    }
}

// fold fc biases through G0: g_bT = b_txt@G0, g_bI = b_img@G0 (warp per column)
__global__ void k_bias(const float* __restrict__ tb, const float* __restrict__ ib,
                       const float* __restrict__ g0) {
    int gw = (blockIdx.x * blockDim.x + threadIdx.x) >> 5;   // 0..2047
    int lane = threadIdx.x & 31;
    if (gw >= 2048) return;
    int col = gw & 1023;
    const float* bv = (gw < 1024) ? tb : ib;
    float s = 0.f;
#pragma unroll 4
    for (int j = lane; j < 1024; j += 32)
        s += bv[j] * g0[(size_t)j * 1024 + col];
#pragma unroll
    for (int o = 16; o; o >>= 1) s += __shfl_xor_sync(0xffffffffu, s, o);
    if (lane == 0) { if (gw < 1024) g_bT[col] = s; else g_bI[col] = s; }
}

// ---------------- pipelined mma.sync bf16x3 GEMM ----------------
// gridDim.z > 1 enables split-K (cMode 1 -> atomicAdd into pre-zeroed F rows).
// preset 1: fused weight precompute (x<3: TXTF; else IMGF), grid (19, 8).
// preset 2: fused layer-0 (y<68: text rows; else image rows), grid (8, 70).
#define SROW 40
#define TILEB (128 * SROW * 2)
#define STAGEB (4 * TILEB)
#define SMEM_GEMM (2 * STAGEB)

__global__ __launch_bounds__(256, 2)
void mma_gemm(int nChunks, int KP, size_t bOff,
              int aSel, int cMode, int ldC, size_t cOff,
              int cntSel, int cntImm, int aListSel, int outListSel,
              int biasSel, const float* __restrict__ alp, const float* __restrict__ arp,
              int NH, int skipImg, int preset) {
    const float* al = alp;
    const float* ar = arp;
    int row0 = blockIdx.y * 128;
    int col0 = blockIdx.x * 128;

    if (preset == 1) {
        aSel = 4; cMode = 4; KP = 1024; nChunks = 32;
        cntSel = 0; cntImm = 1024; aListSel = 0; outListSel = 0;
        biasSel = 0; al = nullptr; skipImg = 0;
        if (blockIdx.x < 3) { bOff = OFF_TXTP; cOff = OFF_TXTF; ldC = 384;
                              col0 = blockIdx.x * 128; }
        else                { bOff = OFF_IMGP; cOff = OFF_IMGF; ldC = 2048;
                              col0 = (blockIdx.x - 3) * 128; }
    } else if (preset == 2) {
        cMode = 1; ldC = 1024; cntSel = 0; NH = 4;
        if (blockIdx.y < 68) {
            aSel = 1; KP = 384; nChunks = 12; bOff = OFF_TXTF; cntImm = NND;
            aListSel = 0; outListSel = 0; biasSel = 1; skipImg = 1;
            row0 = blockIdx.y * 128;
        } else {
            aSel = 3; KP = 2048; nChunks = 64; bOff = OFF_IMGF; cntImm = 256;
            aListSel = 0; outListSel = 5; biasSel = 2; skipImg = 0;
            row0 = (blockIdx.y - 68) * 128;
        }
    }

    const int* cp = sel_cnt(cntSel);
    int cnt = cp ? *cp : cntImm;
    if (row0 >= cnt) return;
    int chunkBase = blockIdx.z * nChunks;
    bool splitK = gridDim.z > 1;

    extern __shared__ char sm[];
    uint32_t sb = smem_u32(sm);

    const __nv_bfloat16* Ah = sel_Ah(aSel);
    const __nv_bfloat16* Al = sel_Al(aSel);
    const __nv_bfloat16* Bh = g_Bh + bOff;
    const __nv_bfloat16* Bl = g_Bl + bOff;
    const int* alist = sel_list(aListSel);

    int tid = threadIdx.x, lane = tid & 31, wid = tid >> 5;
    int wm = wid & 1, wn = wid >> 1;

    float acc[4][4][4];
#pragma unroll
    for (int i = 0; i < 4; i++)
#pragma unroll
        for (int j = 0; j < 4; j++)
#pragma unroll
            for (int q = 0; q < 4; q++) acc[i][j][q] = 0.f;

    int lrow = tid >> 2;
    int lk   = (tid & 3) * 8;

    int arow0g = 0, arow1g = 0; int av0 = 0, av1 = 0;
    {
        int r0 = row0 + lrow, r1 = row0 + lrow + 64;
        if (r0 < cnt) { av0 = 16; arow0g = alist ? alist[r0] : r0; }
        if (r1 < cnt) { av1 = 16; arow1g = alist ? alist[r1] : r1; }
    }
    int brow0 = col0 + lrow, brow1 = col0 + lrow + 64;

#define LOAD_CHUNK(c, s) do {                                                   \
        int k0g = (chunkBase + (c)) * 32;                                       \
        uint32_t st = sb + (s) * STAGEB;                                        \
        uint32_t d0 = st + (uint32_t)(lrow * SROW + lk) * 2;                    \
        uint32_t d1 = st + (uint32_t)((lrow + 64) * SROW + lk) * 2;             \
        cpa16(d0,             Ah + (size_t)arow0g * KP + k0g + lk, av0);        \
        cpa16(d1,             Ah + (size_t)arow1g * KP + k0g + lk, av1);        \
        cpa16(d0 + TILEB,     Al + (size_t)arow0g * KP + k0g + lk, av0);        \
        cpa16(d1 + TILEB,     Al + (size_t)arow1g * KP + k0g + lk, av1);        \
        cpa16(d0 + 2 * TILEB, Bh + (size_t)brow0 * KP + k0g + lk, 16);          \
        cpa16(d1 + 2 * TILEB, Bh + (size_t)brow1 * KP + k0g + lk, 16);          \
        cpa16(d0 + 3 * TILEB, Bl + (size_t)brow0 * KP + k0g + lk, 16);          \
        cpa16(d1 + 3 * TILEB, Bl + (size_t)brow1 * KP + k0g + lk, 16);          \
        cpa_commit();                                                           \
    } while (0)

    int aR = (lane & 15), aC = (lane >> 4) << 3;
    int bR = (lane & 7),  bC = ((lane >> 3) & 1) << 3;

    LOAD_CHUNK(0, 0);
    for (int c = 0; c < nChunks; c++) {
        if (c + 1 < nChunks) {
            LOAD_CHUNK(c + 1, (c + 1) & 1);
            cpa_wait<1>();
        } else {
            cpa_wait<0>();
        }
        __syncthreads();
        uint32_t st = sb + (uint32_t)(c & 1) * STAGEB;
#pragma unroll
        for (int ks = 0; ks < 2; ks++) {
            int k0 = ks * 16;
            uint32_t a[4][4], bh[4][2], bl[4][2];
            uint32_t aoff[4];
#pragma unroll
            for (int am = 0; am < 4; am++) {
                aoff[am] = st + (uint32_t)((wm * 64 + am * 16 + aR) * SROW + k0 + aC) * 2;
                ldsm_x4(a[am], aoff[am]);
            }
#pragma unroll
            for (int bn = 0; bn < 4; bn++) {
                uint32_t off = st + (uint32_t)((wn * 32 + bn * 8 + bR) * SROW + k0 + bC) * 2;
                ldsm_x2(bh[bn], off + 2 * TILEB);
                ldsm_x2(bl[bn], off + 3 * TILEB);
            }
#pragma unroll
            for (int am = 0; am < 4; am++)
#pragma unroll
                for (int bn = 0; bn < 4; bn++)
                    mma16816(acc[am][bn], a[am], bh[bn]);
#pragma unroll
            for (int am = 0; am < 4; am++)
#pragma unroll
                for (int bn = 0; bn < 4; bn++)
                    mma16816(acc[am][bn], a[am], bl[bn]);
#pragma unroll
            for (int am = 0; am < 4; am++)
                ldsm_x4(a[am], aoff[am] + TILEB);
#pragma unroll
            for (int am = 0; am < 4; am++)
#pragma unroll
                for (int bn = 0; bn < 4; bn++)
                    mma16816(acc[am][bn], a[am], bh[bn]);
        }
        __syncthreads();
    }
#undef LOAD_CHUNK

    // ---------------- epilogue ----------------
    const int* ol = sel_list(outListSel);
    const float* bias = (biasSel == 1) ? g_bT : ((biasSel == 2) ? g_bI : nullptr);
    int h = 0;
    if (al) h = (col0 + wn * 32) / (ldC / NH);

#pragma unroll
    for (int am = 0; am < 4; am++) {
#pragma unroll
        for (int part = 0; part < 2; part++) {
            int r = row0 + wm * 64 + am * 16 + (lane >> 2) + part * 8;
            bool valid = r < cnt;
            int orow = 0;
            if (valid) {
                if (outListSel == 5)      orow = img_row(r);
                else if (ol)              orow = ol[r];
                else                      orow = r;
            }
            // image rows are owned by the image-path blocks; suppress BOTH the
            // store and elr here so concurrent text/image blocks never collide.
            if (valid && skipImg) {
                int p = orow % PER_;
                if (p >= W_ && p < W_ + I_) valid = false;
            }
            bool doE = valid && (al != nullptr);
            float sl = 0.f, sr = 0.f;
#pragma unroll
            for (int bn = 0; bn < 4; bn++) {
                int cidx = col0 + wn * 32 + bn * 8 + (lane & 3) * 2;
                float x = acc[am][bn][part * 2 + 0];
                float y = acc[am][bn][part * 2 + 1];
                if (bias) { x += bias[cidx]; y += bias[cidx + 1]; }
                if (doE) {
                    sl += x * al[cidx] + y * al[cidx + 1];
                    sr += x * ar[cidx] + y * ar[cidx + 1];
                }
                if (valid) {
                    if (cMode == 1) {
                        float* dst = &g_F[(size_t)orow * ldC + cidx];
                        if (splitK) {
                            atomicAdd(dst, x);
                            atomicAdd(dst + 1, y);
                        } else {
                            float2 v; v.x = x; v.y = y;
                            *(float2*)dst = v;
                        }
                    } else if (cMode == 2) {
                        size_t o = (size_t)orow * 1024 + cidx;
                        __nv_bfloat16 hx = __float2bfloat16(x);
                        __nv_bfloat16 hy = __float2bfloat16(y);
                        __nv_bfloat162 H; H.x = hx; H.y = hy;
                        __nv_bfloat162 L;
                        L.x = __float2bfloat16(x - __bfloat162float(hx));
                        L.y = __float2bfloat16(y - __bfloat162float(hy));
                        *(__nv_bfloat162*)&g_Abh[o] = H;
                        *(__nv_bfloat162*)&g_Abl[o] = L;
                    } else {
                        size_t o = cOff + (size_t)orow * ldC + cidx;
                        __nv_bfloat16 hx = __float2bfloat16(x);
                        __nv_bfloat16 hy = __float2bfloat16(y);
                        __nv_bfloat162 H; H.x = hx; H.y = hy;
                        __nv_bfloat162 L;
                        L.x = __float2bfloat16(x - __bfloat162float(hx));
                        L.y = __float2bfloat16(y - __bfloat162float(hy));
                        *(__nv_bfloat162*)&g_Bh[o] = H;
                        *(__nv_bfloat162*)&g_Bl[o] = L;
                    }
                }
            }
            if (al) {
                sl += __shfl_xor_sync(0xffffffffu, sl, 1);
                sl += __shfl_xor_sync(0xffffffffu, sl, 2);
                sr += __shfl_xor_sync(0xffffffffu, sr, 1);
                sr += __shfl_xor_sync(0xffffffffu, sr, 2);
                if (doE && (lane & 3) == 0) {
                    atomicAdd(&g_EL[orow * NH + h], sl);
                    atomicAdd(&g_ER[orow * NH + h], sr);
                }
            }
        }
    }
}

// ---------------- sets/CSR ----------------
__global__ void k_init() {
    int i = blockIdx.x * blockDim.x + threadIdx.x;
    if (i < NND) {
        g_A1f[i] = 0; g_R1f[i] = 0;
        g_deg[i] = 0;
#pragma unroll
        for (int h = 0; h < 4; h++) { g_EL[i * 4 + h] = 0.f; g_ER[i * 4 + h] = 0.f; }
    }
    if (i == NND) g_deg[NND] = 0;
    if (i == 0) { g_cnt1 = 0; g_cntR = 0; }
}
__global__ void k_markA1(const int* __restrict__ src, const int* __restrict__ dst,
                         const int* __restrict__ sid, int E) {
    int e = blockIdx.x * blockDim.x + threadIdx.x;
    if (e < E) {
        int d = dst[e];
        if (d == sid[0] || d == sid[1] || d == sid[2] || d == sid[3])
            g_A1f[src[e]] = 1;
    }
}
__global__ void k_markR1(const int* __restrict__ src, const int* __restrict__ dst, int E) {
    int e = blockIdx.x * blockDim.x + threadIdx.x;
    if (e < E && g_A1f[dst[e]]) g_R1f[src[e]] = 1;
}
__global__ void k_compact_count(const int* __restrict__ dst, int E) {
    int i = blockIdx.x * blockDim.x + threadIdx.x;
    if (i < NND) {
        if (g_A1f[i]) g_list1[atomicAdd(&g_cnt1, 1)] = i;
        if (g_R1f[i]) g_listR[atomicAdd(&g_cntR, 1)] = i;
    }
    if (i < E) atomicAdd(&g_deg[dst[i]], 1);
}
__global__ void k_scan() {
    __shared__ int sh[1024];
    int tid = threadIdx.x;
    const int chunk = (NND + 1023) >> 10;
    int lo = tid * chunk;
    int hi = lo + chunk; if (hi > NND) hi = NND; if (lo > NND) lo = NND;
    int sum = 0;
    for (int i = lo; i < hi; i++) sum += g_deg[i];
    sh[tid] = sum; __syncthreads();
    for (int d = 1; d < 1024; d <<= 1) {
        int v = 0;
        if (tid >= d) v = sh[tid - d];
        __syncthreads();
        if (tid >= d) sh[tid] += v;
        __syncthreads();
    }
    int run = (tid == 0) ? 0 : sh[tid - 1];
    for (int i = lo; i < hi; i++) {
        g_off[i] = run; g_cur[i] = run; run += g_deg[i];
    }
    if (tid == 1023) g_off[NND] = run;
}
__global__ void k_fill(const int* __restrict__ src, const int* __restrict__ dst, int E) {
    int e = blockIdx.x * blockDim.x + threadIdx.x;
    if (e < E) {
        int p = atomicAdd(&g_cur[dst[e]], 1);
        g_esrc[p] = src[e];
    }
}

// zero EL/ER (stride NH) and F rows (width ldF) for a compacted list
__global__ void k_zeroELR(int which, int NH, int ldF) {
    int n = (which == 1) ? g_cnt1 : g_cntR;
    const int* list = (which == 1) ? g_list1 : g_listR;
    long total = (long)n * ldF;
    long stride = (long)gridDim.x * blockDim.x;
    for (long i = (long)blockIdx.x * blockDim.x + threadIdx.x; i < total; i += stride) {
        int idx = (int)(i / ldF);
        int c = (int)(i - (long)idx * ldF);
        int nd = list[idx];
        g_F[(size_t)nd * ldF + c] = 0.f;
        if (c < NH) { g_EL[nd * NH + c] = 0.f; g_ER[nd * NH + c] = 0.f; }
    }
}

// ---------------- GAT attention ----------------
template <int NH, int DD, bool ACT>
__global__ void k_attn(const float* __restrict__ bias, int outMode,
                       int listSel, int cntSel, int cntImm,
                       const int* __restrict__ extList, float* __restrict__ extOut) {
    constexpr int WID = NH * DD;
    constexpr int NE  = WID / 128;
    constexpr int CE  = 128 / NH;
    const int* cp = sel_cnt(cntSel);
    int cnt = cp ? *cp : cntImm;
    const int* list = (listSel == 3) ? extList : sel_list(listSel);
    int tid = threadIdx.x;

    __shared__ float s_er[NH], s_m[NH], s_iz[NH];
    __shared__ float red[128];
    __shared__ float swt[32 * NH];
    __shared__ int   ssrc[32];

    for (int bi = blockIdx.x; bi < cnt; bi += gridDim.x) {
        int nd = list ? list[bi] : bi;
        int lo  = g_off[nd];
        int deg = g_off[nd + 1] - lo;

        if (tid < NH) s_er[tid] = g_ER[nd * NH + tid];
        __syncthreads();

        int h  = tid / CE;
        int e0 = tid % CE;
        float erh = s_er[h];

        float lmax = -1e30f;
        for (int e = e0; e < deg; e += CE) {
            int s = g_esrc[lo + e];
            float x = g_EL[s * NH + h] + erh;
            x = x > 0.f ? x : 0.2f * x;
            lmax = fmaxf(lmax, x);
        }
        red[tid] = lmax; __syncthreads();
#pragma unroll
        for (int st = CE / 2; st > 0; st >>= 1) {
            if (e0 < st) red[tid] = fmaxf(red[tid], red[tid + st]);
            __syncthreads();
        }
        if (e0 == 0) s_m[h] = red[tid];
        __syncthreads();
        float mh = s_m[h];

        float lsum = 0.f;
        for (int e = e0; e < deg; e += CE) {
            int s = g_esrc[lo + e];
            float x = g_EL[s * NH + h] + erh;
            x = x > 0.f ? x : 0.2f * x;
            lsum += expf(x - mh);
        }
        red[tid] = lsum; __syncthreads();
#pragma unroll
        for (int st = CE / 2; st > 0; st >>= 1) {
            if (e0 < st) red[tid] += red[tid + st];
            __syncthreads();
        }
        if (e0 == 0) s_iz[h] = 1.f / red[tid];
        __syncthreads();

        float accv[NE];
        int hd[NE];
#pragma unroll
        for (int j = 0; j < NE; j++) { accv[j] = 0.f; hd[j] = (tid + j * 128) / DD; }

        for (int base = 0; base < deg; base += 32) {
            int mcnt = deg - base; if (mcnt > 32) mcnt = 32;
            if (tid < 32 * NH) {
                int eL = tid / NH, hh = tid - (tid / NH) * NH;
                float wv = 0.f;
                if (eL < mcnt) {
                    int s = g_esrc[lo + base + eL];
                    float x = g_EL[s * NH + hh] + s_er[hh];
                    x = x > 0.f ? x : 0.2f * x;
                    wv = expf(x - s_m[hh]) * s_iz[hh];
                    if (hh == 0) ssrc[eL] = s;
                }
                swt[eL * NH + hh] = wv;
            }
            __syncthreads();
            for (int eL = 0; eL < mcnt; eL++) {
                int s = ssrc[eL];
                const float* fr = g_F + (size_t)s * WID;
#pragma unroll
                for (int j = 0; j < NE; j++)
                    accv[j] += swt[eL * NH + hd[j]] * fr[tid + j * 128];
            }
            __syncthreads();
        }

#pragma unroll
        for (int j = 0; j < NE; j++) {
            int c = tid + j * 128;
            float v = accv[j] + bias[c];
            if (ACT) v = v > 0.f ? v : (expf(v) - 1.f);
            if (outMode == 3) {
                extOut[(size_t)bi * WID + c] = v;
            } else {
                __nv_bfloat16* dh = (outMode == 1 ? g_Aah : g_Abh);
                __nv_bfloat16* dl = (outMode == 1 ? g_Aal : g_Abl);
                split_store(dh + (size_t)nd * 1024 + c, dl + (size_t)nd * 1024 + c, v);
            }
        }
    }
}

// ---------------- launch ----------------
extern "C" void kernel_launch(void* const* d_in, const int* in_sizes, int n_in,
                              void* d_out, int out_size) {
    const int*   all_words      = (const int*)  d_in[0];
    const float* image_feats    = (const float*)d_in[1];
    const int*   sentences      = (const int*)  d_in[2];
    const float* sentence_mask  = (const float*)d_in[3];
    const int*   utterances     = (const int*)  d_in[4];
    const float* utterance_mask = (const float*)d_in[5];
    const int*   session_ids    = (const int*)  d_in[6];
    const int*   edge_src       = (const int*)  d_in[7];
    const int*   edge_dst       = (const int*)  d_in[8];
    const float* word_embed     = (const float*)d_in[9];
    const float* text_fc_w      = (const float*)d_in[10];
    const float* text_fc_b      = (const float*)d_in[11];
    const float* image_fc_w     = (const float*)d_in[12];
    const float* image_fc_b     = (const float*)d_in[13];
    const float* gat0_fc = (const float*)d_in[14];
    const float* gat0_al = (const float*)d_in[15];
    const float* gat0_ar = (const float*)d_in[16];
    const float* gat0_b  = (const float*)d_in[17];
    const float* gat1_fc = (const float*)d_in[18];
    const float* gat1_al = (const float*)d_in[19];
    const float* gat1_ar = (const float*)d_in[20];
    const float* gat1_b  = (const float*)d_in[21];
    const float* gat2_fc = (const float*)d_in[22];
    const float* gat2_al = (const float*)d_in[23];
    const float* gat2_ar = (const float*)d_in[24];
    const float* gat2_b  = (const float*)d_in[25];
    float* out = (float*)d_out;
    int E = in_sizes[7];

    cudaFuncSetAttribute(mma_gemm, cudaFuncAttributeMaxDynamicSharedMemorySize, SMEM_GEMM);

    // features + weight prep
    k_feat1<<<NND, 128>>>(all_words, sentences, sentence_mask, word_embed);
    k_feat23<<<BB * (U_ + 1), 128>>>(utterances, utterance_mask);
    k_splitWall<<<dim3(32, 64, 5), dim3(32, 8)>>>(gat0_fc, gat1_fc, gat2_fc,
                                                  text_fc_w, image_fc_w);
    k_bias<<<256, 256>>>(text_fc_b, image_fc_b, gat0_fc);
    k_splitImg<<<512, 256>>>(image_feats);

    // sets + CSR (also zeroes EL/ER for layer 0)
    k_init<<<(NND + 256) / 256, 256>>>();
    k_markA1<<<(E + 255) / 256, 256>>>(edge_src, edge_dst, session_ids, E);
    k_markR1<<<(E + 255) / 256, 256>>>(edge_src, edge_dst, E);
    k_compact_count<<<(E + 255) / 256, 256>>>(edge_dst, E);
    k_scan<<<1, 1024>>>();
    k_fill<<<(E + 255) / 256, 256>>>(edge_src, edge_dst, E);

    // fused weight precompute: TXTF (x<3) + IMGF (x>=3) in ONE launch
    mma_gemm<<<dim3(19, 8), 256, SMEM_GEMM>>>(0, 0, 0, 0, 0, 0, 0,
                                              0, 0, 0, 0, 0, nullptr, nullptr,
                                              1, 0, 1);
    // fused layer-0 f: text rows (y<68) + image rows (y>=68) in ONE launch
    mma_gemm<<<dim3(8, 70), 256, SMEM_GEMM>>>(0, 0, 0, 0, 0, 0, 0,
                                              0, 0, 0, 0, 0, gat0_al, gat0_ar,
                                              4, 0, 2);
    k_attn<4, 256, true><<<2176, 128>>>(gat0_b, 1, 2, 2, 0, nullptr, nullptr);

    // layer 1: zero EL/ER + F rows(listR), then split-K=2 GEMM (atomicAdd into F)
    k_zeroELR<<<256, 256>>>(2, 4, 1024);
    mma_gemm<<<dim3(8, 68, 2), 256, SMEM_GEMM>>>(16, 1024, OFF_G1, 1, 1, 1024, 0,
                                                 2, 0, 2, 2, 0, gat1_al, gat1_ar,
                                                 4, 0, 0);
    k_attn<4, 256, true><<<2176, 128>>>(gat1_b, 2, 1, 1, 0, nullptr, nullptr);

    // layer 2: zero EL/ER + F rows(list1), then split-K=4 GEMM
    k_zeroELR<<<64, 256>>>(1, 1, 512);
    mma_gemm<<<dim3(4, 68, 4), 256, SMEM_GEMM>>>(8, 1024, OFF_G2, 2, 1, 512, 0,
                                                 1, 0, 1, 1, 0, gat2_al, gat2_ar,
                                                 1, 0, 0);
    k_attn<1, 512, false><<<32, 128>>>(gat2_b, 3, 3, 0, BB, session_ids, out);
}